// round 1
// baseline (speedup 1.0000x reference)
#include <cuda_runtime.h>

#define NB 2
#define NH 16
#define SS 2048
#define DK 64
#define DM 1024
#define MROWS (NB*SS)   // 4096

// Scratch (allocation-free rule: __device__ globals)
__device__ float g_qh[NB*NH*SS*DK];   // [B,H,S,Dk]
__device__ float g_kh[NB*NH*SS*DK];
__device__ float g_vh[NB*NH*SS*DK];
__device__ float g_ctx[(size_t)MROWS*DM]; // [B*S, D]

// ---------------------------------------------------------------------------
// GEMM NN: C[M=4096, N=1024] = A[4096,1024] @ W[1024,1024] + bias
// 128x128 tile, BK=8, 256 threads, 8x8 microtile.
// mode 0: scatter to head layout [B,H,S,Dk]; mode 1: plain row-major out.
// ---------------------------------------------------------------------------
__global__ void __launch_bounds__(256) gemm_nn_kernel(
    const float* __restrict__ A, const float* __restrict__ W,
    const float* __restrict__ bias, float* __restrict__ out, int mode)
{
    __shared__ float As[8][128];
    __shared__ float Bs[8][128];
    const int tid  = threadIdx.x;
    const int brow = blockIdx.y * 128;
    const int bcol = blockIdx.x * 128;
    const int tx = tid & 15;
    const int ty = tid >> 4;

    const int a_row = tid >> 1;
    const int a_col = (tid & 1) << 2;
    const int b_row = tid >> 5;
    const int b_col = (tid & 31) << 2;

    float acc[8][8];
    #pragma unroll
    for (int i = 0; i < 8; i++)
        #pragma unroll
        for (int j = 0; j < 8; j++) acc[i][j] = 0.f;

    for (int k0 = 0; k0 < DM; k0 += 8) {
        float4 av = *(const float4*)(A + (size_t)(brow + a_row) * DM + k0 + a_col);
        As[a_col+0][a_row] = av.x;
        As[a_col+1][a_row] = av.y;
        As[a_col+2][a_row] = av.z;
        As[a_col+3][a_row] = av.w;
        *(float4*)&Bs[b_row][b_col] =
            *(const float4*)(W + (size_t)(k0 + b_row) * DM + bcol + b_col);
        __syncthreads();
        #pragma unroll
        for (int k = 0; k < 8; k++) {
            float4 a0 = *(float4*)&As[k][ty*4];
            float4 a1 = *(float4*)&As[k][64 + ty*4];
            float4 b0 = *(float4*)&Bs[k][tx*4];
            float4 b1 = *(float4*)&Bs[k][64 + tx*4];
            float a[8] = {a0.x,a0.y,a0.z,a0.w,a1.x,a1.y,a1.z,a1.w};
            float b[8] = {b0.x,b0.y,b0.z,b0.w,b1.x,b1.y,b1.z,b1.w};
            #pragma unroll
            for (int i = 0; i < 8; i++)
                #pragma unroll
                for (int j = 0; j < 8; j++)
                    acc[i][j] += a[i] * b[j];
        }
        __syncthreads();
    }

    #pragma unroll
    for (int i = 0; i < 8; i++) {
        int r = brow + ((i < 4) ? (ty*4 + i) : (64 + ty*4 + i - 4));
        #pragma unroll
        for (int j = 0; j < 8; j++) {
            int c = bcol + ((j < 4) ? (tx*4 + j) : (64 + tx*4 + j - 4));
            float val = acc[i][j] + bias[c];
            if (mode == 0) {
                int bb = r >> 11, s = r & (SS-1);
                int h  = c >> 6,  dk = c & (DK-1);
                out[((size_t)(bb*NH + h) * SS + s) * DK + dk] = val;
            } else {
                out[(size_t)r * DM + c] = val;
            }
        }
    }
}

// ---------------------------------------------------------------------------
// Scores (batched NT): S[bh][i][j] = dot(QH[bh][i], KH[bh][j]) / 8
// per bh: M=N=2048, K=64. 128x128 tile, BK=16, 8x8 microtile.
// ---------------------------------------------------------------------------
__global__ void __launch_bounds__(256) scores_kernel(float* __restrict__ attn)
{
    __shared__ float As[16][128];
    __shared__ float Bs[16][128];
    const int tid = threadIdx.x;
    const int bh  = blockIdx.z;
    const float* Q  = g_qh + (size_t)bh * SS * DK;
    const float* Kp = g_kh + (size_t)bh * SS * DK;
    float* C = attn + (size_t)bh * SS * SS;
    const int brow = blockIdx.y * 128;
    const int bcol = blockIdx.x * 128;
    const int tx = tid & 15;
    const int ty = tid >> 4;
    const int l_row = tid >> 2;        // 0..63
    const int l_col = (tid & 3) << 2;  // 0,4,8,12

    float acc[8][8];
    #pragma unroll
    for (int i = 0; i < 8; i++)
        #pragma unroll
        for (int j = 0; j < 8; j++) acc[i][j] = 0.f;

    for (int k0 = 0; k0 < DK; k0 += 16) {
        #pragma unroll
        for (int half = 0; half < 2; half++) {
            int row = l_row + half * 64;
            float4 av = *(const float4*)(Q  + (size_t)(brow + row) * DK + k0 + l_col);
            As[l_col+0][row] = av.x; As[l_col+1][row] = av.y;
            As[l_col+2][row] = av.z; As[l_col+3][row] = av.w;
            float4 bv = *(const float4*)(Kp + (size_t)(bcol + row) * DK + k0 + l_col);
            Bs[l_col+0][row] = bv.x; Bs[l_col+1][row] = bv.y;
            Bs[l_col+2][row] = bv.z; Bs[l_col+3][row] = bv.w;
        }
        __syncthreads();
        #pragma unroll
        for (int k = 0; k < 16; k++) {
            float4 a0 = *(float4*)&As[k][ty*4];
            float4 a1 = *(float4*)&As[k][64 + ty*4];
            float4 b0 = *(float4*)&Bs[k][tx*4];
            float4 b1 = *(float4*)&Bs[k][64 + tx*4];
            float a[8] = {a0.x,a0.y,a0.z,a0.w,a1.x,a1.y,a1.z,a1.w};
            float b[8] = {b0.x,b0.y,b0.z,b0.w,b1.x,b1.y,b1.z,b1.w};
            #pragma unroll
            for (int i = 0; i < 8; i++)
                #pragma unroll
                for (int j = 0; j < 8; j++)
                    acc[i][j] += a[i] * b[j];
        }
        __syncthreads();
    }

    const float inv = 0.125f;
    #pragma unroll
    for (int i = 0; i < 8; i++) {
        int r = brow + ((i < 4) ? (ty*4 + i) : (64 + ty*4 + i - 4));
        float4 s0 = make_float4(acc[i][0]*inv, acc[i][1]*inv, acc[i][2]*inv, acc[i][3]*inv);
        float4 s1 = make_float4(acc[i][4]*inv, acc[i][5]*inv, acc[i][6]*inv, acc[i][7]*inv);
        *(float4*)&C[(size_t)r * SS + bcol + tx*4]      = s0;
        *(float4*)&C[(size_t)r * SS + bcol + 64 + tx*4] = s1;
    }
}

// ---------------------------------------------------------------------------
// Softmax: one block per row of 2048; row held in registers (8 floats/thread).
// ---------------------------------------------------------------------------
__global__ void __launch_bounds__(256) softmax_kernel(float* __restrict__ attn)
{
    __shared__ float redm[8];
    __shared__ float reds[8];
    const int tid = threadIdx.x;
    float* p = attn + (size_t)blockIdx.x * SS;

    float4 v0 = *(float4*)&p[tid*8];
    float4 v1 = *(float4*)&p[tid*8 + 4];

    float m = fmaxf(fmaxf(fmaxf(v0.x, v0.y), fmaxf(v0.z, v0.w)),
                    fmaxf(fmaxf(v1.x, v1.y), fmaxf(v1.z, v1.w)));
    #pragma unroll
    for (int o = 16; o > 0; o >>= 1) m = fmaxf(m, __shfl_xor_sync(0xffffffffu, m, o));
    if ((tid & 31) == 0) redm[tid >> 5] = m;
    __syncthreads();
    float rowmax = redm[0];
    #pragma unroll
    for (int i = 1; i < 8; i++) rowmax = fmaxf(rowmax, redm[i]);

    v0.x = __expf(v0.x - rowmax); v0.y = __expf(v0.y - rowmax);
    v0.z = __expf(v0.z - rowmax); v0.w = __expf(v0.w - rowmax);
    v1.x = __expf(v1.x - rowmax); v1.y = __expf(v1.y - rowmax);
    v1.z = __expf(v1.z - rowmax); v1.w = __expf(v1.w - rowmax);

    float s = v0.x + v0.y + v0.z + v0.w + v1.x + v1.y + v1.z + v1.w;
    #pragma unroll
    for (int o = 16; o > 0; o >>= 1) s += __shfl_xor_sync(0xffffffffu, s, o);
    if ((tid & 31) == 0) reds[tid >> 5] = s;
    __syncthreads();
    float rowsum = 0.f;
    #pragma unroll
    for (int i = 0; i < 8; i++) rowsum += reds[i];
    float invs = 1.0f / rowsum;

    v0.x *= invs; v0.y *= invs; v0.z *= invs; v0.w *= invs;
    v1.x *= invs; v1.y *= invs; v1.z *= invs; v1.w *= invs;
    *(float4*)&p[tid*8]     = v0;
    *(float4*)&p[tid*8 + 4] = v1;
}

// ---------------------------------------------------------------------------
// PV (batched NN): CTX[bh][i][:] = W[bh][i][:] @ V[bh]   (M=2048,N=64,K=2048)
// 128x64 tile, BK=16, 256 threads, 8x4 microtile. Scatter ctx to [B*S, D].
// ---------------------------------------------------------------------------
__global__ void __launch_bounds__(256) pv_kernel(const float* __restrict__ attn)
{
    __shared__ float As[16][128];
    __shared__ float Bs[16][64];
    const int tid = threadIdx.x;
    const int bh  = blockIdx.y;
    const int b = bh >> 4, h = bh & 15;
    const float* Aw = attn + (size_t)bh * SS * SS;
    const float* V  = g_vh + (size_t)bh * SS * DK;
    const int brow = blockIdx.x * 128;
    const int tx = tid & 15;
    const int ty = tid >> 4;
    const int a_row = tid >> 2;
    const int a_col = (tid & 3) << 2;
    const int b_row = tid >> 4;        // 0..15
    const int b_col = (tid & 15) << 2; // 0..60

    float acc[8][4];
    #pragma unroll
    for (int i = 0; i < 8; i++)
        #pragma unroll
        for (int j = 0; j < 4; j++) acc[i][j] = 0.f;

    for (int k0 = 0; k0 < SS; k0 += 16) {
        #pragma unroll
        for (int half = 0; half < 2; half++) {
            int row = a_row + half * 64;
            float4 av = *(const float4*)(Aw + (size_t)(brow + row) * SS + k0 + a_col);
            As[a_col+0][row] = av.x; As[a_col+1][row] = av.y;
            As[a_col+2][row] = av.z; As[a_col+3][row] = av.w;
        }
        *(float4*)&Bs[b_row][b_col] =
            *(const float4*)(V + (size_t)(k0 + b_row) * DK + b_col);
        __syncthreads();
        #pragma unroll
        for (int k = 0; k < 16; k++) {
            float4 a0 = *(float4*)&As[k][ty*4];
            float4 a1 = *(float4*)&As[k][64 + ty*4];
            float4 b0 = *(float4*)&Bs[k][tx*4];
            float a[8] = {a0.x,a0.y,a0.z,a0.w,a1.x,a1.y,a1.z,a1.w};
            float bb[4] = {b0.x,b0.y,b0.z,b0.w};
            #pragma unroll
            for (int i = 0; i < 8; i++)
                #pragma unroll
                for (int j = 0; j < 4; j++)
                    acc[i][j] += a[i] * bb[j];
        }
        __syncthreads();
    }

    #pragma unroll
    for (int i = 0; i < 8; i++) {
        int s = brow + ((i < 4) ? (ty*4 + i) : (64 + ty*4 + i - 4));
        float4 st = make_float4(acc[i][0], acc[i][1], acc[i][2], acc[i][3]);
        *(float4*)&g_ctx[(size_t)(b*SS + s) * DM + h*DK + tx*4] = st;
    }
}

// ---------------------------------------------------------------------------
extern "C" void kernel_launch(void* const* d_in, const int* in_sizes, int n_in,
                              void* d_out, int out_size)
{
    const float* q  = (const float*)d_in[0];
    const float* k  = (const float*)d_in[1];
    const float* v  = (const float*)d_in[2];
    const float* Wq = (const float*)d_in[3];
    const float* bq = (const float*)d_in[4];
    const float* Wk = (const float*)d_in[5];
    const float* bk = (const float*)d_in[6];
    const float* Wv = (const float*)d_in[7];
    const float* bv = (const float*)d_in[8];
    const float* Wo = (const float*)d_in[9];
    const float* bo = (const float*)d_in[10];

    float* out  = (float*)d_out;
    float* attn = out + (size_t)MROWS * DM;   // attn_weights after output

    void *qh, *kh, *vh, *ctx;
    cudaGetSymbolAddress(&qh,  g_qh);
    cudaGetSymbolAddress(&kh,  g_kh);
    cudaGetSymbolAddress(&vh,  g_vh);
    cudaGetSymbolAddress(&ctx, g_ctx);

    dim3 blk(256);
    // QKV projections -> head layout
    gemm_nn_kernel<<<dim3(8, 32), blk>>>(q, Wq, bq, (float*)qh, 0);
    gemm_nn_kernel<<<dim3(8, 32), blk>>>(k, Wk, bk, (float*)kh, 0);
    gemm_nn_kernel<<<dim3(8, 32), blk>>>(v, Wv, bv, (float*)vh, 0);
    // Scores = QK^T / sqrt(dk), written straight into the attn output slot
    scores_kernel<<<dim3(16, 16, 32), blk>>>(attn);
    // Softmax in place (these normalized weights ARE output #2)
    softmax_kernel<<<NB * NH * SS, blk>>>(attn);
    // ctx = attn @ V, scattered back to [B*S, D]
    pv_kernel<<<dim3(16, 32), blk>>>(attn);
    // output = ctx @ Wo + bo
    gemm_nn_kernel<<<dim3(8, 32), blk>>>((const float*)ctx, Wo, bo, out, 1);
}

// round 2
// speedup vs baseline: 1.0509x; 1.0509x over previous
#include <cuda_runtime.h>

#define NB 2
#define NH 16
#define SS 2048
#define DK 64
#define DM 1024
#define MROWS (NB*SS)   // 4096

// Scratch (allocation-free rule: __device__ globals)
__device__ float g_qh[NB*NH*SS*DK];   // [B,H,S,Dk]
__device__ float g_kh[NB*NH*SS*DK];
__device__ float g_vh[NB*NH*SS*DK];
__device__ float g_ctx[(size_t)MROWS*DM]; // [B*S, D]

// ---------------------------------------------------------------------------
// GEMM NN: C[M=4096, N=1024] = A[4096,1024] @ W[1024,1024] + bias
// 128x128 tile, BK=16, double-buffered smem, 256 threads, 8x8 microtile.
// mode 0: scatter to head layout [B,H,S,Dk]; mode 1: plain row-major out.
// ---------------------------------------------------------------------------
__global__ void __launch_bounds__(256, 2) gemm_nn_kernel(
    const float* __restrict__ A, const float* __restrict__ W,
    const float* __restrict__ bias, float* __restrict__ out, int mode)
{
    __shared__ float As[2][16][128];
    __shared__ float Bs[2][16][128];
    const int tid  = threadIdx.x;
    const int brow = blockIdx.y * 128;
    const int bcol = blockIdx.x * 128;
    const int tx = tid & 15;
    const int ty = tid >> 4;

    const int a_row = tid >> 1;          // 0..127
    const int a_col = (tid & 1) << 3;    // 0 or 8
    const int b_row = tid >> 4;          // 0..15
    const int b_col = (tid & 15) << 3;   // 0..120

    const float* Ap = A + (size_t)(brow + a_row) * DM + a_col;
    const float* Bp = W + (size_t)b_row * DM + bcol + b_col;

    float acc[8][8];
    #pragma unroll
    for (int i = 0; i < 8; i++)
        #pragma unroll
        for (int j = 0; j < 8; j++) acc[i][j] = 0.f;

    float4 ra0 = *(const float4*)(Ap);
    float4 ra1 = *(const float4*)(Ap + 4);
    float4 rb0 = *(const float4*)(Bp);
    float4 rb1 = *(const float4*)(Bp + 4);

    As[0][a_col+0][a_row] = ra0.x; As[0][a_col+1][a_row] = ra0.y;
    As[0][a_col+2][a_row] = ra0.z; As[0][a_col+3][a_row] = ra0.w;
    As[0][a_col+4][a_row] = ra1.x; As[0][a_col+5][a_row] = ra1.y;
    As[0][a_col+6][a_row] = ra1.z; As[0][a_col+7][a_row] = ra1.w;
    *(float4*)&Bs[0][b_row][b_col]     = rb0;
    *(float4*)&Bs[0][b_row][b_col + 4] = rb1;
    __syncthreads();

    int buf = 0;
    for (int k0 = 16; k0 <= DM; k0 += 16) {
        const bool more = (k0 < DM);
        if (more) {
            ra0 = *(const float4*)(Ap + k0);
            ra1 = *(const float4*)(Ap + k0 + 4);
            rb0 = *(const float4*)(Bp + (size_t)k0 * DM);
            rb1 = *(const float4*)(Bp + (size_t)k0 * DM + 4);
        }
        #pragma unroll
        for (int k = 0; k < 16; k++) {
            float4 a0 = *(float4*)&As[buf][k][ty*4];
            float4 a1 = *(float4*)&As[buf][k][64 + ty*4];
            float4 b0 = *(float4*)&Bs[buf][k][tx*4];
            float4 b1 = *(float4*)&Bs[buf][k][64 + tx*4];
            float a[8] = {a0.x,a0.y,a0.z,a0.w,a1.x,a1.y,a1.z,a1.w};
            float b[8] = {b0.x,b0.y,b0.z,b0.w,b1.x,b1.y,b1.z,b1.w};
            #pragma unroll
            for (int i = 0; i < 8; i++)
                #pragma unroll
                for (int j = 0; j < 8; j++)
                    acc[i][j] += a[i] * b[j];
        }
        if (more) {
            __syncthreads();
            const int nb = buf ^ 1;
            As[nb][a_col+0][a_row] = ra0.x; As[nb][a_col+1][a_row] = ra0.y;
            As[nb][a_col+2][a_row] = ra0.z; As[nb][a_col+3][a_row] = ra0.w;
            As[nb][a_col+4][a_row] = ra1.x; As[nb][a_col+5][a_row] = ra1.y;
            As[nb][a_col+6][a_row] = ra1.z; As[nb][a_col+7][a_row] = ra1.w;
            *(float4*)&Bs[nb][b_row][b_col]     = rb0;
            *(float4*)&Bs[nb][b_row][b_col + 4] = rb1;
            __syncthreads();
            buf = nb;
        }
    }

    #pragma unroll
    for (int i = 0; i < 8; i++) {
        int r = brow + ((i < 4) ? (ty*4 + i) : (64 + ty*4 + i - 4));
        #pragma unroll
        for (int j = 0; j < 8; j++) {
            int c = bcol + ((j < 4) ? (tx*4 + j) : (64 + tx*4 + j - 4));
            float val = acc[i][j] + bias[c];
            if (mode == 0) {
                int bb = r >> 11, s = r & (SS-1);
                int h  = c >> 6,  dk = c & (DK-1);
                out[((size_t)(bb*NH + h) * SS + s) * DK + dk] = val;
            } else {
                out[(size_t)r * DM + c] = val;
            }
        }
    }
}

// ---------------------------------------------------------------------------
// Scores (batched NT): S[bh][i][j] = dot(QH[bh][i], KH[bh][j]) / 8
// per bh: M=N=2048, K=64. 128x128 tile, BK=16, double-buffered, 8x8 microtile.
// ---------------------------------------------------------------------------
__global__ void __launch_bounds__(256, 2) scores_kernel(float* __restrict__ attn)
{
    __shared__ float As[2][16][128];
    __shared__ float Bs[2][16][128];
    const int tid = threadIdx.x;
    const int bh  = blockIdx.z;
    const float* Q  = g_qh + (size_t)bh * SS * DK;
    const float* Kp = g_kh + (size_t)bh * SS * DK;
    float* C = attn + (size_t)bh * SS * SS;
    const int brow = blockIdx.y * 128;
    const int bcol = blockIdx.x * 128;
    const int tx = tid & 15;
    const int ty = tid >> 4;

    const int l_row = tid >> 1;        // 0..127
    const int l_col = (tid & 1) << 3;  // 0 or 8

    const float* Qp = Q  + (size_t)(brow + l_row) * DK + l_col;
    const float* Kq = Kp + (size_t)(bcol + l_row) * DK + l_col;

    float acc[8][8];
    #pragma unroll
    for (int i = 0; i < 8; i++)
        #pragma unroll
        for (int j = 0; j < 8; j++) acc[i][j] = 0.f;

    float4 ra0 = *(const float4*)(Qp);
    float4 ra1 = *(const float4*)(Qp + 4);
    float4 rb0 = *(const float4*)(Kq);
    float4 rb1 = *(const float4*)(Kq + 4);

    As[0][l_col+0][l_row] = ra0.x; As[0][l_col+1][l_row] = ra0.y;
    As[0][l_col+2][l_row] = ra0.z; As[0][l_col+3][l_row] = ra0.w;
    As[0][l_col+4][l_row] = ra1.x; As[0][l_col+5][l_row] = ra1.y;
    As[0][l_col+6][l_row] = ra1.z; As[0][l_col+7][l_row] = ra1.w;
    Bs[0][l_col+0][l_row] = rb0.x; Bs[0][l_col+1][l_row] = rb0.y;
    Bs[0][l_col+2][l_row] = rb0.z; Bs[0][l_col+3][l_row] = rb0.w;
    Bs[0][l_col+4][l_row] = rb1.x; Bs[0][l_col+5][l_row] = rb1.y;
    Bs[0][l_col+6][l_row] = rb1.z; Bs[0][l_col+7][l_row] = rb1.w;
    __syncthreads();

    int buf = 0;
    for (int k0 = 16; k0 <= DK; k0 += 16) {
        const bool more = (k0 < DK);
        if (more) {
            ra0 = *(const float4*)(Qp + k0);
            ra1 = *(const float4*)(Qp + k0 + 4);
            rb0 = *(const float4*)(Kq + k0);
            rb1 = *(const float4*)(Kq + k0 + 4);
        }
        #pragma unroll
        for (int k = 0; k < 16; k++) {
            float4 a0 = *(float4*)&As[buf][k][ty*4];
            float4 a1 = *(float4*)&As[buf][k][64 + ty*4];
            float4 b0 = *(float4*)&Bs[buf][k][tx*4];
            float4 b1 = *(float4*)&Bs[buf][k][64 + tx*4];
            float a[8] = {a0.x,a0.y,a0.z,a0.w,a1.x,a1.y,a1.z,a1.w};
            float b[8] = {b0.x,b0.y,b0.z,b0.w,b1.x,b1.y,b1.z,b1.w};
            #pragma unroll
            for (int i = 0; i < 8; i++)
                #pragma unroll
                for (int j = 0; j < 8; j++)
                    acc[i][j] += a[i] * b[j];
        }
        if (more) {
            __syncthreads();
            const int nb = buf ^ 1;
            As[nb][l_col+0][l_row] = ra0.x; As[nb][l_col+1][l_row] = ra0.y;
            As[nb][l_col+2][l_row] = ra0.z; As[nb][l_col+3][l_row] = ra0.w;
            As[nb][l_col+4][l_row] = ra1.x; As[nb][l_col+5][l_row] = ra1.y;
            As[nb][l_col+6][l_row] = ra1.z; As[nb][l_col+7][l_row] = ra1.w;
            Bs[nb][l_col+0][l_row] = rb0.x; Bs[nb][l_col+1][l_row] = rb0.y;
            Bs[nb][l_col+2][l_row] = rb0.z; Bs[nb][l_col+3][l_row] = rb0.w;
            Bs[nb][l_col+4][l_row] = rb1.x; Bs[nb][l_col+5][l_row] = rb1.y;
            Bs[nb][l_col+6][l_row] = rb1.z; Bs[nb][l_col+7][l_row] = rb1.w;
            __syncthreads();
            buf = nb;
        }
    }

    const float inv = 0.125f;
    #pragma unroll
    for (int i = 0; i < 8; i++) {
        int r = brow + ((i < 4) ? (ty*4 + i) : (64 + ty*4 + i - 4));
        float4 s0 = make_float4(acc[i][0]*inv, acc[i][1]*inv, acc[i][2]*inv, acc[i][3]*inv);
        float4 s1 = make_float4(acc[i][4]*inv, acc[i][5]*inv, acc[i][6]*inv, acc[i][7]*inv);
        *(float4*)&C[(size_t)r * SS + bcol + tx*4]      = s0;
        *(float4*)&C[(size_t)r * SS + bcol + 64 + tx*4] = s1;
    }
}

// ---------------------------------------------------------------------------
// Softmax: one block per row of 2048; row held in registers (8 floats/thread).
// ---------------------------------------------------------------------------
__global__ void __launch_bounds__(256) softmax_kernel(float* __restrict__ attn)
{
    __shared__ float redm[8];
    __shared__ float reds[8];
    const int tid = threadIdx.x;
    float* p = attn + (size_t)blockIdx.x * SS;

    float4 v0 = *(float4*)&p[tid*8];
    float4 v1 = *(float4*)&p[tid*8 + 4];

    float m = fmaxf(fmaxf(fmaxf(v0.x, v0.y), fmaxf(v0.z, v0.w)),
                    fmaxf(fmaxf(v1.x, v1.y), fmaxf(v1.z, v1.w)));
    #pragma unroll
    for (int o = 16; o > 0; o >>= 1) m = fmaxf(m, __shfl_xor_sync(0xffffffffu, m, o));
    if ((tid & 31) == 0) redm[tid >> 5] = m;
    __syncthreads();
    float rowmax = redm[0];
    #pragma unroll
    for (int i = 1; i < 8; i++) rowmax = fmaxf(rowmax, redm[i]);

    v0.x = __expf(v0.x - rowmax); v0.y = __expf(v0.y - rowmax);
    v0.z = __expf(v0.z - rowmax); v0.w = __expf(v0.w - rowmax);
    v1.x = __expf(v1.x - rowmax); v1.y = __expf(v1.y - rowmax);
    v1.z = __expf(v1.z - rowmax); v1.w = __expf(v1.w - rowmax);

    float s = v0.x + v0.y + v0.z + v0.w + v1.x + v1.y + v1.z + v1.w;
    #pragma unroll
    for (int o = 16; o > 0; o >>= 1) s += __shfl_xor_sync(0xffffffffu, s, o);
    if ((tid & 31) == 0) reds[tid >> 5] = s;
    __syncthreads();
    float rowsum = 0.f;
    #pragma unroll
    for (int i = 0; i < 8; i++) rowsum += reds[i];
    float invs = 1.0f / rowsum;

    v0.x *= invs; v0.y *= invs; v0.z *= invs; v0.w *= invs;
    v1.x *= invs; v1.y *= invs; v1.z *= invs; v1.w *= invs;
    *(float4*)&p[tid*8]     = v0;
    *(float4*)&p[tid*8 + 4] = v1;
}

// ---------------------------------------------------------------------------
// PV (batched NN): CTX[bh][i][:] = W[bh][i][:] @ V[bh]   (M=2048,N=64,K=2048)
// 128x64 tile, BK=32, double-buffered, 256 threads, 8x4 microtile.
// ---------------------------------------------------------------------------
__global__ void __launch_bounds__(256, 2) pv_kernel(const float* __restrict__ attn)
{
    __shared__ float As[2][32][128];
    __shared__ float Bs[2][32][64];
    const int tid = threadIdx.x;
    const int bh  = blockIdx.y;
    const int b = bh >> 4, h = bh & 15;
    const float* Aw = attn + (size_t)bh * SS * SS;
    const float* V  = g_vh + (size_t)bh * SS * DK;
    const int brow = blockIdx.x * 128;
    const int tx = tid & 15;
    const int ty = tid >> 4;

    const int a_row = tid >> 1;          // 0..127
    const int a_col = (tid & 1) << 4;    // 0 or 16
    const int b_row = tid >> 3;          // 0..31
    const int b_col = (tid & 7) << 3;    // 0..56

    const float* Ap = Aw + (size_t)(brow + a_row) * SS + a_col;
    const float* Vp = V  + (size_t)b_row * DK + b_col;

    float acc[8][4];
    #pragma unroll
    for (int i = 0; i < 8; i++)
        #pragma unroll
        for (int j = 0; j < 4; j++) acc[i][j] = 0.f;

    float4 ra[4], rb[2];
    #pragma unroll
    for (int q = 0; q < 4; q++) ra[q] = *(const float4*)(Ap + q*4);
    rb[0] = *(const float4*)(Vp);
    rb[1] = *(const float4*)(Vp + 4);

    #pragma unroll
    for (int q = 0; q < 4; q++) {
        As[0][a_col + q*4 + 0][a_row] = ra[q].x;
        As[0][a_col + q*4 + 1][a_row] = ra[q].y;
        As[0][a_col + q*4 + 2][a_row] = ra[q].z;
        As[0][a_col + q*4 + 3][a_row] = ra[q].w;
    }
    *(float4*)&Bs[0][b_row][b_col]     = rb[0];
    *(float4*)&Bs[0][b_row][b_col + 4] = rb[1];
    __syncthreads();

    int buf = 0;
    for (int k0 = 32; k0 <= SS; k0 += 32) {
        const bool more = (k0 < SS);
        if (more) {
            #pragma unroll
            for (int q = 0; q < 4; q++) ra[q] = *(const float4*)(Ap + k0 + q*4);
            rb[0] = *(const float4*)(Vp + (size_t)k0 * DK);
            rb[1] = *(const float4*)(Vp + (size_t)k0 * DK + 4);
        }
        #pragma unroll
        for (int k = 0; k < 32; k++) {
            float4 a0 = *(float4*)&As[buf][k][ty*4];
            float4 a1 = *(float4*)&As[buf][k][64 + ty*4];
            float4 b0 = *(float4*)&Bs[buf][k][tx*4];
            float a[8] = {a0.x,a0.y,a0.z,a0.w,a1.x,a1.y,a1.z,a1.w};
            float bb[4] = {b0.x,b0.y,b0.z,b0.w};
            #pragma unroll
            for (int i = 0; i < 8; i++)
                #pragma unroll
                for (int j = 0; j < 4; j++)
                    acc[i][j] += a[i] * bb[j];
        }
        if (more) {
            __syncthreads();
            const int nb = buf ^ 1;
            #pragma unroll
            for (int q = 0; q < 4; q++) {
                As[nb][a_col + q*4 + 0][a_row] = ra[q].x;
                As[nb][a_col + q*4 + 1][a_row] = ra[q].y;
                As[nb][a_col + q*4 + 2][a_row] = ra[q].z;
                As[nb][a_col + q*4 + 3][a_row] = ra[q].w;
            }
            *(float4*)&Bs[nb][b_row][b_col]     = rb[0];
            *(float4*)&Bs[nb][b_row][b_col + 4] = rb[1];
            __syncthreads();
            buf = nb;
        }
    }

    #pragma unroll
    for (int i = 0; i < 8; i++) {
        int s = brow + ((i < 4) ? (ty*4 + i) : (64 + ty*4 + i - 4));
        float4 st = make_float4(acc[i][0], acc[i][1], acc[i][2], acc[i][3]);
        *(float4*)&g_ctx[(size_t)(b*SS + s) * DM + h*DK + tx*4] = st;
    }
}

// ---------------------------------------------------------------------------
extern "C" void kernel_launch(void* const* d_in, const int* in_sizes, int n_in,
                              void* d_out, int out_size)
{
    const float* q  = (const float*)d_in[0];
    const float* k  = (const float*)d_in[1];
    const float* v  = (const float*)d_in[2];
    const float* Wq = (const float*)d_in[3];
    const float* bq = (const float*)d_in[4];
    const float* Wk = (const float*)d_in[5];
    const float* bk = (const float*)d_in[6];
    const float* Wv = (const float*)d_in[7];
    const float* bv = (const float*)d_in[8];
    const float* Wo = (const float*)d_in[9];
    const float* bo = (const float*)d_in[10];

    float* out  = (float*)d_out;
    float* attn = out + (size_t)MROWS * DM;   // attn_weights after output

    void *qh, *kh, *vh, *ctx;
    cudaGetSymbolAddress(&qh,  g_qh);
    cudaGetSymbolAddress(&kh,  g_kh);
    cudaGetSymbolAddress(&vh,  g_vh);
    cudaGetSymbolAddress(&ctx, g_ctx);

    dim3 blk(256);
    // QKV projections -> head layout
    gemm_nn_kernel<<<dim3(8, 32), blk>>>(q, Wq, bq, (float*)qh, 0);
    gemm_nn_kernel<<<dim3(8, 32), blk>>>(k, Wk, bk, (float*)kh, 0);
    gemm_nn_kernel<<<dim3(8, 32), blk>>>(v, Wv, bv, (float*)vh, 0);
    // Scores = QK^T / sqrt(dk), written straight into the attn output slot
    scores_kernel<<<dim3(16, 16, 32), blk>>>(attn);
    // Softmax in place (these normalized weights ARE output #2)
    softmax_kernel<<<NB * NH * SS, blk>>>(attn);
    // ctx = attn @ V, scattered back to [B*S, D]
    pv_kernel<<<dim3(16, 32), blk>>>(attn);
    // output = ctx @ Wo + bo
    gemm_nn_kernel<<<dim3(8, 32), blk>>>((const float*)ctx, Wo, bo, out, 1);
}

// round 3
// speedup vs baseline: 1.1702x; 1.1135x over previous
#include <cuda_runtime.h>

#define NB 2
#define NH 16
#define SS 2048
#define DK 64
#define DM 1024
#define MROWS (NB*SS)   // 4096

// Scratch (allocation-free rule: __device__ globals)
__device__ float g_qh[NB*NH*SS*DK];   // [B,H,S,Dk]
__device__ float g_kh[NB*NH*SS*DK];
__device__ float g_vh[NB*NH*SS*DK];
__device__ float g_ctx[(size_t)MROWS*DM]; // [B*S, D]

// ---- packed fp32x2 helpers (sm_10x; ptxas never emits these from C++) ----
__device__ __forceinline__ void ffma2(unsigned long long& d,
                                      unsigned long long a,
                                      unsigned long long b) {
    asm("fma.rn.f32x2 %0, %1, %2, %0;" : "+l"(d) : "l"(a), "l"(b));
}
__device__ __forceinline__ unsigned long long dup2(float x) {
    unsigned long long r;
    unsigned u = __float_as_uint(x);
    asm("mov.b64 %0, {%1, %1};" : "=l"(r) : "r"(u));
    return r;
}
__device__ __forceinline__ float lo2(unsigned long long v) {
    return __uint_as_float((unsigned)v);
}
__device__ __forceinline__ float hi2(unsigned long long v) {
    return __uint_as_float((unsigned)(v >> 32));
}

// ---------------------------------------------------------------------------
// GEMM NN: C[M=4096, N=1024] = A[4096,1024] @ W[1024,1024] + bias
// 128x128 tile, BK=16, double-buffered, 256 threads, 8x8 microtile (FFMA2,
// paired over rows). mode 0: scatter to [B,H,S,Dk]; mode 1: row-major.
// ---------------------------------------------------------------------------
__global__ void __launch_bounds__(256, 2) gemm_nn_kernel(
    const float* __restrict__ A, const float* __restrict__ W,
    const float* __restrict__ bias, float* __restrict__ out, int mode)
{
    __shared__ __align__(16) float As[2][16][128];
    __shared__ __align__(16) float Bs[2][16][128];
    const int tid  = threadIdx.x;
    const int brow = blockIdx.y * 128;
    const int bcol = blockIdx.x * 128;
    const int tx = tid & 15;
    const int ty = tid >> 4;

    const int a_row = tid >> 1;          // 0..127
    const int a_col = (tid & 1) << 3;    // 0 or 8
    const int b_row = tid >> 4;          // 0..15
    const int b_col = (tid & 15) << 3;   // 0..120

    const float* Ap = A + (size_t)(brow + a_row) * DM + a_col;
    const float* Bp = W + (size_t)b_row * DM + bcol + b_col;

    unsigned long long acc[4][8];        // row-pairs x 8 cols
    #pragma unroll
    for (int i = 0; i < 4; i++)
        #pragma unroll
        for (int j = 0; j < 8; j++) acc[i][j] = 0ULL;

    float4 ra0 = *(const float4*)(Ap);
    float4 ra1 = *(const float4*)(Ap + 4);
    float4 rb0 = *(const float4*)(Bp);
    float4 rb1 = *(const float4*)(Bp + 4);

    As[0][a_col+0][a_row] = ra0.x; As[0][a_col+1][a_row] = ra0.y;
    As[0][a_col+2][a_row] = ra0.z; As[0][a_col+3][a_row] = ra0.w;
    As[0][a_col+4][a_row] = ra1.x; As[0][a_col+5][a_row] = ra1.y;
    As[0][a_col+6][a_row] = ra1.z; As[0][a_col+7][a_row] = ra1.w;
    *(float4*)&Bs[0][b_row][b_col]     = rb0;
    *(float4*)&Bs[0][b_row][b_col + 4] = rb1;
    __syncthreads();

    int buf = 0;
    for (int k0 = 16; k0 <= DM; k0 += 16) {
        const bool more = (k0 < DM);
        if (more) {
            ra0 = *(const float4*)(Ap + k0);
            ra1 = *(const float4*)(Ap + k0 + 4);
            rb0 = *(const float4*)(Bp + (size_t)k0 * DM);
            rb1 = *(const float4*)(Bp + (size_t)k0 * DM + 4);
        }
        #pragma unroll
        for (int k = 0; k < 16; k++) {
            ulonglong2 av0 = *(ulonglong2*)&As[buf][k][ty*4];
            ulonglong2 av1 = *(ulonglong2*)&As[buf][k][64 + ty*4];
            float4 b0 = *(float4*)&Bs[buf][k][tx*4];
            float4 b1 = *(float4*)&Bs[buf][k][64 + tx*4];
            unsigned long long ap[4] = {av0.x, av0.y, av1.x, av1.y};
            unsigned long long bd[8] = {dup2(b0.x), dup2(b0.y), dup2(b0.z), dup2(b0.w),
                                        dup2(b1.x), dup2(b1.y), dup2(b1.z), dup2(b1.w)};
            #pragma unroll
            for (int i = 0; i < 4; i++)
                #pragma unroll
                for (int j = 0; j < 8; j++)
                    ffma2(acc[i][j], ap[i], bd[j]);
        }
        if (more) {
            __syncthreads();
            const int nb = buf ^ 1;
            As[nb][a_col+0][a_row] = ra0.x; As[nb][a_col+1][a_row] = ra0.y;
            As[nb][a_col+2][a_row] = ra0.z; As[nb][a_col+3][a_row] = ra0.w;
            As[nb][a_col+4][a_row] = ra1.x; As[nb][a_col+5][a_row] = ra1.y;
            As[nb][a_col+6][a_row] = ra1.z; As[nb][a_col+7][a_row] = ra1.w;
            *(float4*)&Bs[nb][b_row][b_col]     = rb0;
            *(float4*)&Bs[nb][b_row][b_col + 4] = rb1;
            __syncthreads();
            buf = nb;
        }
    }

    #pragma unroll
    for (int ip = 0; ip < 4; ip++) {
        int rbase = (ip < 2) ? (ty*4 + 2*ip) : (64 + ty*4 + 2*(ip - 2));
        #pragma unroll
        for (int half = 0; half < 2; half++) {
            int r = brow + rbase + half;
            #pragma unroll
            for (int j = 0; j < 8; j++) {
                int c = bcol + ((j < 4) ? (tx*4 + j) : (64 + tx*4 + j - 4));
                float val = (half ? hi2(acc[ip][j]) : lo2(acc[ip][j])) + bias[c];
                if (mode == 0) {
                    int bb = r >> 11, s = r & (SS-1);
                    int h  = c >> 6,  dk = c & (DK-1);
                    out[((size_t)(bb*NH + h) * SS + s) * DK + dk] = val;
                } else {
                    out[(size_t)r * DM + c] = val;
                }
            }
        }
    }
}

// ---------------------------------------------------------------------------
// Scores (batched NT): S[bh][i][j] = dot(QH[bh][i], KH[bh][j]) / 8
// per bh: M=N=2048, K=64. 128x128 tile, BK=16, double-buffered, FFMA2.
// ---------------------------------------------------------------------------
__global__ void __launch_bounds__(256, 2) scores_kernel(float* __restrict__ attn)
{
    __shared__ __align__(16) float As[2][16][128];
    __shared__ __align__(16) float Bs[2][16][128];
    const int tid = threadIdx.x;
    const int bh  = blockIdx.z;
    const float* Q  = g_qh + (size_t)bh * SS * DK;
    const float* Kp = g_kh + (size_t)bh * SS * DK;
    float* C = attn + (size_t)bh * SS * SS;
    const int brow = blockIdx.y * 128;
    const int bcol = blockIdx.x * 128;
    const int tx = tid & 15;
    const int ty = tid >> 4;

    const int l_row = tid >> 1;        // 0..127
    const int l_col = (tid & 1) << 3;  // 0 or 8

    const float* Qp = Q  + (size_t)(brow + l_row) * DK + l_col;
    const float* Kq = Kp + (size_t)(bcol + l_row) * DK + l_col;

    unsigned long long acc[4][8];
    #pragma unroll
    for (int i = 0; i < 4; i++)
        #pragma unroll
        for (int j = 0; j < 8; j++) acc[i][j] = 0ULL;

    float4 ra0 = *(const float4*)(Qp);
    float4 ra1 = *(const float4*)(Qp + 4);
    float4 rb0 = *(const float4*)(Kq);
    float4 rb1 = *(const float4*)(Kq + 4);

    As[0][l_col+0][l_row] = ra0.x; As[0][l_col+1][l_row] = ra0.y;
    As[0][l_col+2][l_row] = ra0.z; As[0][l_col+3][l_row] = ra0.w;
    As[0][l_col+4][l_row] = ra1.x; As[0][l_col+5][l_row] = ra1.y;
    As[0][l_col+6][l_row] = ra1.z; As[0][l_col+7][l_row] = ra1.w;
    Bs[0][l_col+0][l_row] = rb0.x; Bs[0][l_col+1][l_row] = rb0.y;
    Bs[0][l_col+2][l_row] = rb0.z; Bs[0][l_col+3][l_row] = rb0.w;
    Bs[0][l_col+4][l_row] = rb1.x; Bs[0][l_col+5][l_row] = rb1.y;
    Bs[0][l_col+6][l_row] = rb1.z; Bs[0][l_col+7][l_row] = rb1.w;
    __syncthreads();

    int buf = 0;
    for (int k0 = 16; k0 <= DK; k0 += 16) {
        const bool more = (k0 < DK);
        if (more) {
            ra0 = *(const float4*)(Qp + k0);
            ra1 = *(const float4*)(Qp + k0 + 4);
            rb0 = *(const float4*)(Kq + k0);
            rb1 = *(const float4*)(Kq + k0 + 4);
        }
        #pragma unroll
        for (int k = 0; k < 16; k++) {
            ulonglong2 av0 = *(ulonglong2*)&As[buf][k][ty*4];
            ulonglong2 av1 = *(ulonglong2*)&As[buf][k][64 + ty*4];
            float4 b0 = *(float4*)&Bs[buf][k][tx*4];
            float4 b1 = *(float4*)&Bs[buf][k][64 + tx*4];
            unsigned long long ap[4] = {av0.x, av0.y, av1.x, av1.y};
            unsigned long long bd[8] = {dup2(b0.x), dup2(b0.y), dup2(b0.z), dup2(b0.w),
                                        dup2(b1.x), dup2(b1.y), dup2(b1.z), dup2(b1.w)};
            #pragma unroll
            for (int i = 0; i < 4; i++)
                #pragma unroll
                for (int j = 0; j < 8; j++)
                    ffma2(acc[i][j], ap[i], bd[j]);
        }
        if (more) {
            __syncthreads();
            const int nb = buf ^ 1;
            As[nb][l_col+0][l_row] = ra0.x; As[nb][l_col+1][l_row] = ra0.y;
            As[nb][l_col+2][l_row] = ra0.z; As[nb][l_col+3][l_row] = ra0.w;
            As[nb][l_col+4][l_row] = ra1.x; As[nb][l_col+5][l_row] = ra1.y;
            As[nb][l_col+6][l_row] = ra1.z; As[nb][l_col+7][l_row] = ra1.w;
            Bs[nb][l_col+0][l_row] = rb0.x; Bs[nb][l_col+1][l_row] = rb0.y;
            Bs[nb][l_col+2][l_row] = rb0.z; Bs[nb][l_col+3][l_row] = rb0.w;
            Bs[nb][l_col+4][l_row] = rb1.x; Bs[nb][l_col+5][l_row] = rb1.y;
            Bs[nb][l_col+6][l_row] = rb1.z; Bs[nb][l_col+7][l_row] = rb1.w;
            __syncthreads();
            buf = nb;
        }
    }

    const float inv = 0.125f;
    #pragma unroll
    for (int ip = 0; ip < 4; ip++) {
        int rbase = (ip < 2) ? (ty*4 + 2*ip) : (64 + ty*4 + 2*(ip - 2));
        #pragma unroll
        for (int half = 0; half < 2; half++) {
            int r = brow + rbase + half;
            float s[8];
            #pragma unroll
            for (int j = 0; j < 8; j++)
                s[j] = (half ? hi2(acc[ip][j]) : lo2(acc[ip][j])) * inv;
            *(float4*)&C[(size_t)r * SS + bcol + tx*4]      = make_float4(s[0], s[1], s[2], s[3]);
            *(float4*)&C[(size_t)r * SS + bcol + 64 + tx*4] = make_float4(s[4], s[5], s[6], s[7]);
        }
    }
}

// ---------------------------------------------------------------------------
// Softmax: one block per row of 2048; row held in registers (8 floats/thread).
// ---------------------------------------------------------------------------
__global__ void __launch_bounds__(256) softmax_kernel(float* __restrict__ attn)
{
    __shared__ float redm[8];
    __shared__ float reds[8];
    const int tid = threadIdx.x;
    float* p = attn + (size_t)blockIdx.x * SS;

    float4 v0 = *(float4*)&p[tid*8];
    float4 v1 = *(float4*)&p[tid*8 + 4];

    float m = fmaxf(fmaxf(fmaxf(v0.x, v0.y), fmaxf(v0.z, v0.w)),
                    fmaxf(fmaxf(v1.x, v1.y), fmaxf(v1.z, v1.w)));
    #pragma unroll
    for (int o = 16; o > 0; o >>= 1) m = fmaxf(m, __shfl_xor_sync(0xffffffffu, m, o));
    if ((tid & 31) == 0) redm[tid >> 5] = m;
    __syncthreads();
    float rowmax = redm[0];
    #pragma unroll
    for (int i = 1; i < 8; i++) rowmax = fmaxf(rowmax, redm[i]);

    v0.x = __expf(v0.x - rowmax); v0.y = __expf(v0.y - rowmax);
    v0.z = __expf(v0.z - rowmax); v0.w = __expf(v0.w - rowmax);
    v1.x = __expf(v1.x - rowmax); v1.y = __expf(v1.y - rowmax);
    v1.z = __expf(v1.z - rowmax); v1.w = __expf(v1.w - rowmax);

    float s = v0.x + v0.y + v0.z + v0.w + v1.x + v1.y + v1.z + v1.w;
    #pragma unroll
    for (int o = 16; o > 0; o >>= 1) s += __shfl_xor_sync(0xffffffffu, s, o);
    if ((tid & 31) == 0) reds[tid >> 5] = s;
    __syncthreads();
    float rowsum = 0.f;
    #pragma unroll
    for (int i = 0; i < 8; i++) rowsum += reds[i];
    float invs = 1.0f / rowsum;

    v0.x *= invs; v0.y *= invs; v0.z *= invs; v0.w *= invs;
    v1.x *= invs; v1.y *= invs; v1.z *= invs; v1.w *= invs;
    *(float4*)&p[tid*8]     = v0;
    *(float4*)&p[tid*8 + 4] = v1;
}

// ---------------------------------------------------------------------------
// PV (batched NN): CTX[bh][i][:] = W[bh][i][:] @ V[bh]   (M=2048,N=64,K=2048)
// 128x64 tile, BK=32, double-buffered, 256 threads, 8x4 microtile (FFMA2).
// ---------------------------------------------------------------------------
__global__ void __launch_bounds__(256, 2) pv_kernel(const float* __restrict__ attn)
{
    __shared__ __align__(16) float As[2][32][128];
    __shared__ __align__(16) float Bs[2][32][64];
    const int tid = threadIdx.x;
    const int bh  = blockIdx.y;
    const int b = bh >> 4, h = bh & 15;
    const float* Aw = attn + (size_t)bh * SS * SS;
    const float* V  = g_vh + (size_t)bh * SS * DK;
    const int brow = blockIdx.x * 128;
    const int tx = tid & 15;
    const int ty = tid >> 4;

    const int a_row = tid >> 1;          // 0..127
    const int a_col = (tid & 1) << 4;    // 0 or 16
    const int b_row = tid >> 3;          // 0..31
    const int b_col = (tid & 7) << 3;    // 0..56

    const float* Ap = Aw + (size_t)(brow + a_row) * SS + a_col;
    const float* Vp = V  + (size_t)b_row * DK + b_col;

    unsigned long long acc[4][4];
    #pragma unroll
    for (int i = 0; i < 4; i++)
        #pragma unroll
        for (int j = 0; j < 4; j++) acc[i][j] = 0ULL;

    float4 ra[4], rb[2];
    #pragma unroll
    for (int q = 0; q < 4; q++) ra[q] = *(const float4*)(Ap + q*4);
    rb[0] = *(const float4*)(Vp);
    rb[1] = *(const float4*)(Vp + 4);

    #pragma unroll
    for (int q = 0; q < 4; q++) {
        As[0][a_col + q*4 + 0][a_row] = ra[q].x;
        As[0][a_col + q*4 + 1][a_row] = ra[q].y;
        As[0][a_col + q*4 + 2][a_row] = ra[q].z;
        As[0][a_col + q*4 + 3][a_row] = ra[q].w;
    }
    *(float4*)&Bs[0][b_row][b_col]     = rb[0];
    *(float4*)&Bs[0][b_row][b_col + 4] = rb[1];
    __syncthreads();

    int buf = 0;
    for (int k0 = 32; k0 <= SS; k0 += 32) {
        const bool more = (k0 < SS);
        if (more) {
            #pragma unroll
            for (int q = 0; q < 4; q++) ra[q] = *(const float4*)(Ap + k0 + q*4);
            rb[0] = *(const float4*)(Vp + (size_t)k0 * DK);
            rb[1] = *(const float4*)(Vp + (size_t)k0 * DK + 4);
        }
        #pragma unroll
        for (int k = 0; k < 32; k++) {
            ulonglong2 av0 = *(ulonglong2*)&As[buf][k][ty*4];
            ulonglong2 av1 = *(ulonglong2*)&As[buf][k][64 + ty*4];
            float4 b0 = *(float4*)&Bs[buf][k][tx*4];
            unsigned long long ap[4] = {av0.x, av0.y, av1.x, av1.y};
            unsigned long long bd[4] = {dup2(b0.x), dup2(b0.y), dup2(b0.z), dup2(b0.w)};
            #pragma unroll
            for (int i = 0; i < 4; i++)
                #pragma unroll
                for (int j = 0; j < 4; j++)
                    ffma2(acc[i][j], ap[i], bd[j]);
        }
        if (more) {
            __syncthreads();
            const int nb = buf ^ 1;
            #pragma unroll
            for (int q = 0; q < 4; q++) {
                As[nb][a_col + q*4 + 0][a_row] = ra[q].x;
                As[nb][a_col + q*4 + 1][a_row] = ra[q].y;
                As[nb][a_col + q*4 + 2][a_row] = ra[q].z;
                As[nb][a_col + q*4 + 3][a_row] = ra[q].w;
            }
            *(float4*)&Bs[nb][b_row][b_col]     = rb[0];
            *(float4*)&Bs[nb][b_row][b_col + 4] = rb[1];
            __syncthreads();
            buf = nb;
        }
    }

    #pragma unroll
    for (int ip = 0; ip < 4; ip++) {
        int sbase = (ip < 2) ? (ty*4 + 2*ip) : (64 + ty*4 + 2*(ip - 2));
        #pragma unroll
        for (int half = 0; half < 2; half++) {
            int s = brow + sbase + half;
            float4 st = half
                ? make_float4(hi2(acc[ip][0]), hi2(acc[ip][1]), hi2(acc[ip][2]), hi2(acc[ip][3]))
                : make_float4(lo2(acc[ip][0]), lo2(acc[ip][1]), lo2(acc[ip][2]), lo2(acc[ip][3]));
            *(float4*)&g_ctx[(size_t)(b*SS + s) * DM + h*DK + tx*4] = st;
        }
    }
}

// ---------------------------------------------------------------------------
extern "C" void kernel_launch(void* const* d_in, const int* in_sizes, int n_in,
                              void* d_out, int out_size)
{
    const float* q  = (const float*)d_in[0];
    const float* k  = (const float*)d_in[1];
    const float* v  = (const float*)d_in[2];
    const float* Wq = (const float*)d_in[3];
    const float* bq = (const float*)d_in[4];
    const float* Wk = (const float*)d_in[5];
    const float* bk = (const float*)d_in[6];
    const float* Wv = (const float*)d_in[7];
    const float* bv = (const float*)d_in[8];
    const float* Wo = (const float*)d_in[9];
    const float* bo = (const float*)d_in[10];

    float* out  = (float*)d_out;
    float* attn = out + (size_t)MROWS * DM;   // attn_weights after output

    void *qh, *kh, *vh, *ctx;
    cudaGetSymbolAddress(&qh,  g_qh);
    cudaGetSymbolAddress(&kh,  g_kh);
    cudaGetSymbolAddress(&vh,  g_vh);
    cudaGetSymbolAddress(&ctx, g_ctx);

    dim3 blk(256);
    // QKV projections -> head layout
    gemm_nn_kernel<<<dim3(8, 32), blk>>>(q, Wq, bq, (float*)qh, 0);
    gemm_nn_kernel<<<dim3(8, 32), blk>>>(k, Wk, bk, (float*)kh, 0);
    gemm_nn_kernel<<<dim3(8, 32), blk>>>(v, Wv, bv, (float*)vh, 0);
    // Scores = QK^T / sqrt(dk), written straight into the attn output slot
    scores_kernel<<<dim3(16, 16, 32), blk>>>(attn);
    // Softmax in place (these normalized weights ARE output #2)
    softmax_kernel<<<NB * NH * SS, blk>>>(attn);
    // ctx = attn @ V, scattered back to [B*S, D]
    pv_kernel<<<dim3(16, 32), blk>>>(attn);
    // output = ctx @ Wo + bo
    gemm_nn_kernel<<<dim3(8, 32), blk>>>((const float*)ctx, Wo, bo, out, 1);
}

// round 5
// speedup vs baseline: 1.4768x; 1.2620x over previous
#include <cuda_runtime.h>
#include <cuda_bf16.h>
#include <cstdint>

#define NB 2
#define NH 16
#define SS 2048
#define DK 64
#define DM 1024
#define NBH (NB*NH)     // 32
#define MROWS (NB*SS)   // 4096

// ---------------- scratch (allocation-free rule) ----------------
__device__ __align__(256) float g_wt[4][DM*DM];     // W^T (K-major) q,k,v,o
__device__ __align__(256) float g_qh[NBH*SS*DK];    // [bh][s][dk]
__device__ __align__(256) float g_kh[NBH*SS*DK];
__device__ __align__(256) float g_vt[NBH*DK*SS];    // [bh][dk][s]
__device__ __align__(256) float g_ctx[(size_t)MROWS*DM];

// ---------------- epilogue modes ----------------
#define EP_F32 0   // out[z*sOb + r*ldo + c] = v*scale (+bias)
#define EP_QK  1   // head layout [bh][s][dk] (+bias)
#define EP_VT  2   // transposed head [bh][dk][s] (+bias)
#define EP_CTX 3   // ctx [b*SS + r][h*64 + c], bh = z

// fp32 -> bf16 hi + residual lo (packed pairs). low half of u32 = first elem.
__device__ __forceinline__ uint32_t split2(float a, float b, uint32_t& lo) {
    __nv_bfloat162 h = __floats2bfloat162_rn(a, b);
    __nv_bfloat162 l = __floats2bfloat162_rn(a - __low2float(h), b - __high2float(h));
    lo = reinterpret_cast<uint32_t&>(l);
    return reinterpret_cast<uint32_t&>(h);
}

__device__ __forceinline__ void mma16816(float* c,
                                         uint32_t a0, uint32_t a1, uint32_t a2, uint32_t a3,
                                         uint32_t b0, uint32_t b1) {
    asm volatile(
        "mma.sync.aligned.m16n8k16.row.col.f32.bf16.bf16.f32 "
        "{%0,%1,%2,%3}, {%4,%5,%6,%7}, {%8,%9}, {%0,%1,%2,%3};"
        : "+f"(c[0]), "+f"(c[1]), "+f"(c[2]), "+f"(c[3])
        : "r"(a0), "r"(a1), "r"(a2), "r"(a3), "r"(b0), "r"(b1));
}

// smem geometry: bf16 rows padded to 40 elems (80 B) -> conflict-free frags
#define LDSTRIDE 40
#define ASZB (128 * LDSTRIDE * 2)          // 10240 B per A matrix

__device__ __forceinline__ void split_store(char* dst_h, char* dst_l, float4 v) {
    uint32_t l0, l1;
    uint32_t h0 = split2(v.x, v.y, l0);
    uint32_t h1 = split2(v.z, v.w, l1);
    *(uint2*)dst_h = make_uint2(h0, h1);
    *(uint2*)dst_l = make_uint2(l0, l1);
}

// ---------------------------------------------------------------------------
// Generic HMMA bf16-split GEMM. C tile 128 x BN, K in chunks of 32.
// A fp32 [., lda] rows m0.. ; B fp32 [., ldb] rows n0.. (both K-major).
// 8 warps: wm = wid&1 (64-row half), wn = wid>>1 (BN/4-wide strip).
// ---------------------------------------------------------------------------
template<int BN>
__global__ void __launch_bounds__(256)
gemm_hmma_kernel(const float* __restrict__ A, int lda, size_t sAb,
                 const float* __restrict__ B, int ldb, size_t sBb,
                 int K,
                 const float* __restrict__ bias,
                 float* __restrict__ out, int ldo, size_t sOb,
                 float scale, int mode)
{
    constexpr int WN = BN / 4;          // warp n-tile
    constexpr int NI = WN / 8;          // 8-col fragments per warp
    constexpr int BSZB = BN * LDSTRIDE * 2;
    constexpr int BHOFF = 2 * ASZB;     // Ah | Al | Bh | Bl
    constexpr int BUFSTR = 2 * ASZB + 2 * BSZB;

    extern __shared__ char sm[];

    const int tid  = threadIdx.x;
    const int wid  = tid >> 5;
    const int lane = tid & 31;
    const int g = lane >> 2;            // fragment group row
    const int t = lane & 3;             // fragment group col
    const int wm = wid & 1;
    const int wn = wid >> 1;

    const int m0 = blockIdx.y * 128;
    const int n0 = blockIdx.x * BN;
    const int z  = blockIdx.z;
    A += (size_t)z * sAb;
    B += (size_t)z * sBb;

    // loader mapping: 2 threads per row, 16 floats each
    const int r    = tid >> 1;          // 0..127
    const int half = tid & 1;
    const float* Ap = A + (size_t)(m0 + r) * lda + half * 16;
    const float* Bp = (r < BN) ? (B + (size_t)(n0 + r) * ldb + half * 16) : nullptr;

    float acc[4][NI][4];
    #pragma unroll
    for (int mi = 0; mi < 4; mi++)
        #pragma unroll
        for (int ni = 0; ni < NI; ni++)
            #pragma unroll
            for (int c = 0; c < 4; c++) acc[mi][ni][c] = 0.f;

    const int nchunk = K >> 5;

    // ---- load chunk 0 into buf 0 ----
    {
        char* bh = sm + (r * LDSTRIDE + half * 16) * 2;
        #pragma unroll
        for (int j = 0; j < 4; j++) {
            float4 v = *(const float4*)(Ap + j * 4);
            split_store(bh + j * 8, bh + ASZB + j * 8, v);
        }
        if (Bp) {
            char* bb = sm + BHOFF + (r * LDSTRIDE + half * 16) * 2;
            #pragma unroll
            for (int j = 0; j < 4; j++) {
                float4 v = *(const float4*)(Bp + j * 4);
                split_store(bb + j * 8, bb + BSZB + j * 8, v);
            }
        }
    }
    __syncthreads();

    for (int c = 0; c < nchunk; c++) {
        const int buf = c & 1;
        const bool more = (c + 1 < nchunk);

        // prefetch next chunk into registers
        float4 pa[4], pb[4];
        if (more) {
            const int k0 = (c + 1) << 5;
            #pragma unroll
            for (int j = 0; j < 4; j++) pa[j] = *(const float4*)(Ap + k0 + j * 4);
            if (Bp) {
                #pragma unroll
                for (int j = 0; j < 4; j++) pb[j] = *(const float4*)(Bp + k0 + j * 4);
            }
        }

        // ---- compute 2 k16 steps from smem[buf] ----
        const char* base = sm + buf * BUFSTR;
        #pragma unroll
        for (int kk = 0; kk < 32; kk += 16) {
            uint32_t bfh[NI][2], bfl[NI][2];
            #pragma unroll
            for (int ni = 0; ni < NI; ni++) {
                const int n = wn * WN + ni * 8 + g;
                const char* pbh = base + BHOFF + (n * LDSTRIDE + kk + 2 * t) * 2;
                bfh[ni][0] = *(const uint32_t*)pbh;
                bfh[ni][1] = *(const uint32_t*)(pbh + 16);
                bfl[ni][0] = *(const uint32_t*)(pbh + BSZB);
                bfl[ni][1] = *(const uint32_t*)(pbh + BSZB + 16);
            }
            #pragma unroll
            for (int mi = 0; mi < 4; mi++) {
                const int row = wm * 64 + mi * 16 + g;
                const char* pah = base + (row * LDSTRIDE + kk + 2 * t) * 2;
                uint32_t ah0 = *(const uint32_t*)pah;
                uint32_t ah1 = *(const uint32_t*)(pah + 8 * LDSTRIDE * 2);
                uint32_t ah2 = *(const uint32_t*)(pah + 16);
                uint32_t ah3 = *(const uint32_t*)(pah + 8 * LDSTRIDE * 2 + 16);
                uint32_t al0 = *(const uint32_t*)(pah + ASZB);
                uint32_t al1 = *(const uint32_t*)(pah + ASZB + 8 * LDSTRIDE * 2);
                uint32_t al2 = *(const uint32_t*)(pah + ASZB + 16);
                uint32_t al3 = *(const uint32_t*)(pah + ASZB + 8 * LDSTRIDE * 2 + 16);
                #pragma unroll
                for (int ni = 0; ni < NI; ni++) {
                    mma16816(acc[mi][ni], ah0, ah1, ah2, ah3, bfh[ni][0], bfh[ni][1]);
                    mma16816(acc[mi][ni], ah0, ah1, ah2, ah3, bfl[ni][0], bfl[ni][1]);
                    mma16816(acc[mi][ni], al0, al1, al2, al3, bfh[ni][0], bfh[ni][1]);
                }
            }
        }

        if (more) {
            __syncthreads();
            char* bh = sm + (buf ^ 1) * BUFSTR + (r * LDSTRIDE + half * 16) * 2;
            #pragma unroll
            for (int j = 0; j < 4; j++)
                split_store(bh + j * 8, bh + ASZB + j * 8, pa[j]);
            if (Bp) {
                char* bb = sm + (buf ^ 1) * BUFSTR + BHOFF + (r * LDSTRIDE + half * 16) * 2;
                #pragma unroll
                for (int j = 0; j < 4; j++)
                    split_store(bb + j * 8, bb + BSZB + j * 8, pb[j]);
            }
            __syncthreads();
        }
    }

    // ---- epilogue from register accumulators ----
    const bool hasb = (bias != nullptr);
    #pragma unroll
    for (int mi = 0; mi < 4; mi++) {
        #pragma unroll
        for (int ni = 0; ni < NI; ni++) {
            const int row0 = m0 + wm * 64 + mi * 16 + g;
            const int row1 = row0 + 8;
            const int col  = n0 + wn * WN + ni * 8 + 2 * t;
            float b0 = hasb ? bias[col]     : 0.f;
            float b1 = hasb ? bias[col + 1] : 0.f;
            float v0 = acc[mi][ni][0] * scale + b0;
            float v1 = acc[mi][ni][1] * scale + b1;
            float v2 = acc[mi][ni][2] * scale + b0;
            float v3 = acc[mi][ni][3] * scale + b1;
            if (mode == EP_F32) {
                float* o = out + (size_t)z * sOb;
                *(float2*)(o + (size_t)row0 * ldo + col) = make_float2(v0, v1);
                *(float2*)(o + (size_t)row1 * ldo + col) = make_float2(v2, v3);
            } else if (mode == EP_QK) {
                int h = col >> 6, dk = col & 63;
                int b_0 = row0 >> 11, s_0 = row0 & (SS - 1);
                int b_1 = row1 >> 11, s_1 = row1 & (SS - 1);
                *(float2*)(out + ((size_t)(b_0 * NH + h) * SS + s_0) * DK + dk) = make_float2(v0, v1);
                *(float2*)(out + ((size_t)(b_1 * NH + h) * SS + s_1) * DK + dk) = make_float2(v2, v3);
            } else if (mode == EP_VT) {
                int h = col >> 6, dk = col & 63;
                int b_0 = row0 >> 11, s_0 = row0 & (SS - 1);
                int b_1 = row1 >> 11, s_1 = row1 & (SS - 1);
                out[((size_t)(b_0 * NH + h) * DK + dk)     * SS + s_0] = v0;
                out[((size_t)(b_0 * NH + h) * DK + dk + 1) * SS + s_0] = v1;
                out[((size_t)(b_1 * NH + h) * DK + dk)     * SS + s_1] = v2;
                out[((size_t)(b_1 * NH + h) * DK + dk + 1) * SS + s_1] = v3;
            } else { // EP_CTX
                int bb = z >> 4, h = z & 15;
                *(float2*)(out + ((size_t)(bb * SS) + row0) * DM + h * DK + col) = make_float2(v0, v1);
                *(float2*)(out + ((size_t)(bb * SS) + row1) * DM + h * DK + col) = make_float2(v2, v3);
            }
        }
    }
}

// ---------------------------------------------------------------------------
// W [K,N] -> W^T [N,K]
// ---------------------------------------------------------------------------
__global__ void transpose_kernel(const float* __restrict__ src, float* __restrict__ dst)
{
    __shared__ float tile[32][33];
    int bx = blockIdx.x * 32, by = blockIdx.y * 32;
    int tx = threadIdx.x, ty = threadIdx.y;
    #pragma unroll
    for (int i = 0; i < 32; i += 8)
        tile[ty + i][tx] = src[(size_t)(by + ty + i) * DM + bx + tx];
    __syncthreads();
    #pragma unroll
    for (int i = 0; i < 32; i += 8)
        dst[(size_t)(bx + ty + i) * DM + by + tx] = tile[tx][ty + i];
}

// ---------------------------------------------------------------------------
// Softmax: one block per row of 2048.
// ---------------------------------------------------------------------------
__global__ void __launch_bounds__(256) softmax_kernel(float* __restrict__ attn)
{
    __shared__ float redm[8];
    __shared__ float reds[8];
    const int tid = threadIdx.x;
    float* p = attn + (size_t)blockIdx.x * SS;

    float4 v0 = *(float4*)&p[tid*8];
    float4 v1 = *(float4*)&p[tid*8 + 4];

    float m = fmaxf(fmaxf(fmaxf(v0.x, v0.y), fmaxf(v0.z, v0.w)),
                    fmaxf(fmaxf(v1.x, v1.y), fmaxf(v1.z, v1.w)));
    #pragma unroll
    for (int o = 16; o > 0; o >>= 1) m = fmaxf(m, __shfl_xor_sync(0xffffffffu, m, o));
    if ((tid & 31) == 0) redm[tid >> 5] = m;
    __syncthreads();
    float rowmax = redm[0];
    #pragma unroll
    for (int i = 1; i < 8; i++) rowmax = fmaxf(rowmax, redm[i]);

    v0.x = __expf(v0.x - rowmax); v0.y = __expf(v0.y - rowmax);
    v0.z = __expf(v0.z - rowmax); v0.w = __expf(v0.w - rowmax);
    v1.x = __expf(v1.x - rowmax); v1.y = __expf(v1.y - rowmax);
    v1.z = __expf(v1.z - rowmax); v1.w = __expf(v1.w - rowmax);

    float s = v0.x + v0.y + v0.z + v0.w + v1.x + v1.y + v1.z + v1.w;
    #pragma unroll
    for (int o = 16; o > 0; o >>= 1) s += __shfl_xor_sync(0xffffffffu, s, o);
    if ((tid & 31) == 0) reds[tid >> 5] = s;
    __syncthreads();
    float rowsum = 0.f;
    #pragma unroll
    for (int i = 0; i < 8; i++) rowsum += reds[i];
    float invs = 1.0f / rowsum;

    v0.x *= invs; v0.y *= invs; v0.z *= invs; v0.w *= invs;
    v1.x *= invs; v1.y *= invs; v1.z *= invs; v1.w *= invs;
    *(float4*)&p[tid*8]     = v0;
    *(float4*)&p[tid*8 + 4] = v1;
}

// ---------------------------------------------------------------------------
extern "C" void kernel_launch(void* const* d_in, const int* in_sizes, int n_in,
                              void* d_out, int out_size)
{
    const float* q  = (const float*)d_in[0];
    const float* k  = (const float*)d_in[1];
    const float* v  = (const float*)d_in[2];
    const float* Wq = (const float*)d_in[3];
    const float* bq = (const float*)d_in[4];
    const float* Wk = (const float*)d_in[5];
    const float* bk = (const float*)d_in[6];
    const float* Wv = (const float*)d_in[7];
    const float* bv = (const float*)d_in[8];
    const float* Wo = (const float*)d_in[9];
    const float* bo = (const float*)d_in[10];

    float* out  = (float*)d_out;
    float* attn = out + (size_t)MROWS * DM;

    void *wt, *qh, *kh, *vt, *ctx;
    cudaGetSymbolAddress(&wt,  g_wt);
    cudaGetSymbolAddress(&qh,  g_qh);
    cudaGetSymbolAddress(&kh,  g_kh);
    cudaGetSymbolAddress(&vt,  g_vt);
    cudaGetSymbolAddress(&ctx, g_ctx);
    float* wtq = (float*)wt;
    float* wtk = wtq + (size_t)DM*DM;
    float* wtv = wtk + (size_t)DM*DM;
    float* wto = wtv + (size_t)DM*DM;

    // dynamic smem sizes
    const int smem128 = 2 * (2*ASZB + 2*128*LDSTRIDE*2);  // 81920
    const int smem64  = 2 * (2*ASZB + 2*64*LDSTRIDE*2);   // 61440
    cudaFuncSetAttribute(gemm_hmma_kernel<128>,
                         cudaFuncAttributeMaxDynamicSharedMemorySize, smem128);
    cudaFuncSetAttribute(gemm_hmma_kernel<64>,
                         cudaFuncAttributeMaxDynamicSharedMemorySize, smem64);

    dim3 tgrid(32, 32), tblk(32, 8);
    transpose_kernel<<<tgrid, tblk>>>(Wq, wtq);
    transpose_kernel<<<tgrid, tblk>>>(Wk, wtk);
    transpose_kernel<<<tgrid, tblk>>>(Wv, wtv);
    transpose_kernel<<<tgrid, tblk>>>(Wo, wto);

    // QKV projections (M=4096, N=1024, K=1024)
    gemm_hmma_kernel<128><<<dim3(8, 32, 1), 256, smem128>>>(
        q, DM, 0, wtq, DM, 0, DM, bq, (float*)qh, 0, 0, 1.f, EP_QK);
    gemm_hmma_kernel<128><<<dim3(8, 32, 1), 256, smem128>>>(
        k, DM, 0, wtk, DM, 0, DM, bk, (float*)kh, 0, 0, 1.f, EP_QK);
    gemm_hmma_kernel<128><<<dim3(8, 32, 1), 256, smem128>>>(
        v, DM, 0, wtv, DM, 0, DM, bv, (float*)vt, 0, 0, 1.f, EP_VT);

    // scores = QK^T / 8 (per bh: M=N=2048, K=64)
    gemm_hmma_kernel<128><<<dim3(16, 16, 32), 256, smem128>>>(
        (const float*)qh, DK, (size_t)SS*DK,
        (const float*)kh, DK, (size_t)SS*DK,
        DK, nullptr, attn, SS, (size_t)SS*SS, 0.125f, EP_F32);

    // softmax in place
    softmax_kernel<<<NBH * SS, 256>>>(attn);

    // ctx = attn @ V (per bh: M=2048, N=64, K=2048)
    gemm_hmma_kernel<64><<<dim3(1, 16, 32), 256, smem64>>>(
        attn, SS, (size_t)SS*SS,
        (const float*)vt, SS, (size_t)DK*SS,
        SS, nullptr, (float*)ctx, 0, 0, 1.f, EP_CTX);

    // out = ctx @ Wo + bo
    gemm_hmma_kernel<128><<<dim3(8, 32, 1), 256, smem128>>>(
        (const float*)ctx, DM, 0, wto, DM, 0, DM, bo, out, DM, 0, 1.f, EP_F32);
}

// round 6
// speedup vs baseline: 1.7232x; 1.1668x over previous
#include <cuda_runtime.h>
#include <cuda_bf16.h>
#include <cstdint>

#define NB 2
#define NH 16
#define SS 2048
#define DK 64
#define DM 1024
#define NBH (NB*NH)     // 32
#define MROWS (NB*SS)   // 4096

// ---------------- scratch (allocation-free rule) ----------------
__device__ __align__(256) float g_wt[4][DM*DM];     // W^T (K-major) q,k,v,o
__device__ __align__(256) float g_qh[NBH*SS*DK];    // [bh][s][dk]
__device__ __align__(256) float g_kh[NBH*SS*DK];
__device__ __align__(256) float g_vt[NBH*DK*SS];    // [bh][dk][s]
__device__ __align__(256) float g_ctx[(size_t)MROWS*DM];

// ---------------- epilogue modes ----------------
#define EP_F32 0   // out[z*sOb + r*ldo + c] = v*scale (+bias)
#define EP_QK  1   // head layout [bh][s][dk] (+bias)
#define EP_VT  2   // transposed head [bh][dk][s] (+bias)
#define EP_CTX 3   // ctx [b*SS + r][h*64 + c], bh = z

// fp32 -> bf16 hi + residual lo (packed pairs). low half of u32 = first elem.
__device__ __forceinline__ uint32_t split2(float a, float b, uint32_t& lo) {
    __nv_bfloat162 h = __floats2bfloat162_rn(a, b);
    __nv_bfloat162 l = __floats2bfloat162_rn(a - __low2float(h), b - __high2float(h));
    lo = reinterpret_cast<uint32_t&>(l);
    return reinterpret_cast<uint32_t&>(h);
}

__device__ __forceinline__ void mma16816(float* c,
                                         uint32_t a0, uint32_t a1, uint32_t a2, uint32_t a3,
                                         uint32_t b0, uint32_t b1) {
    asm volatile(
        "mma.sync.aligned.m16n8k16.row.col.f32.bf16.bf16.f32 "
        "{%0,%1,%2,%3}, {%4,%5,%6,%7}, {%8,%9}, {%0,%1,%2,%3};"
        : "+f"(c[0]), "+f"(c[1]), "+f"(c[2]), "+f"(c[3])
        : "r"(a0), "r"(a1), "r"(a2), "r"(a3), "r"(b0), "r"(b1));
}

__device__ __forceinline__ void ldsm_x4(uint32_t& r0, uint32_t& r1,
                                        uint32_t& r2, uint32_t& r3, uint32_t a) {
    asm volatile("ldmatrix.sync.aligned.m8n8.x4.shared.b16 {%0,%1,%2,%3}, [%4];"
        : "=r"(r0), "=r"(r1), "=r"(r2), "=r"(r3) : "r"(a));
}

// smem geometry: bf16 rows padded to 40 elems (80 B) -> conflict-free frags
#define LDSTRIDE 40
#define ASZB (128 * LDSTRIDE * 2)          // 10240 B per A matrix

__device__ __forceinline__ void split_store(char* dst_h, char* dst_l, float4 v) {
    uint32_t l0, l1;
    uint32_t h0 = split2(v.x, v.y, l0);
    uint32_t h1 = split2(v.z, v.w, l1);
    *(uint2*)dst_h = make_uint2(h0, h1);
    *(uint2*)dst_l = make_uint2(l0, l1);
}

// ---------------------------------------------------------------------------
// Generic HMMA bf16-split GEMM. C tile 128 x BN, K in chunks of 32.
// A fp32 [., lda] rows m0.. ; B fp32 [., ldb] rows n0.. (both K-major).
// 8 warps: wm = wid&1 (64-row half), wn = wid>>1 (BN/4-wide strip).
// Fragments via ldmatrix.x4.
// ---------------------------------------------------------------------------
template<int BN>
__global__ void __launch_bounds__(256)
gemm_hmma_kernel(const float* __restrict__ A, int lda, size_t sAb,
                 const float* __restrict__ B, int ldb, size_t sBb,
                 int K,
                 const float* __restrict__ bias,
                 float* __restrict__ out, int ldo, size_t sOb,
                 float scale, int mode)
{
    constexpr int WN = BN / 4;          // warp n-tile
    constexpr int NI = WN / 8;          // 8-col fragments per warp
    constexpr int NP = NI / 2;          // ldsm.x4 B ops per (hi|lo)
    constexpr int BSZB = BN * LDSTRIDE * 2;
    constexpr int BHOFF = 2 * ASZB;     // Ah | Al | Bh | Bl
    constexpr int BUFSTR = 2 * ASZB + 2 * BSZB;

    extern __shared__ char sm[];
    const uint32_t smu = (uint32_t)__cvta_generic_to_shared(sm);

    const int tid  = threadIdx.x;
    const int wid  = tid >> 5;
    const int lane = tid & 31;
    const int g = lane >> 2;            // fragment group row
    const int t = lane & 3;             // fragment group col
    const int wm = wid & 1;
    const int wn = wid >> 1;

    // ldmatrix lane decomposition
    const int lmat = lane >> 3;         // matrix index 0..3
    const int lr   = lane & 7;          // row within 8x8 matrix
    const int a_row_off = (lmat & 1) * 8 + lr;   // within 16-row A frag
    const int a_k_off   = (lmat >> 1) * 8;       // k halves
    const int b_ni_off  = (lmat >> 1);           // ni within pair
    const int b_k_off   = (lmat & 1) * 8;

    const int m0 = blockIdx.y * 128;
    const int n0 = blockIdx.x * BN;
    const int z  = blockIdx.z;
    A += (size_t)z * sAb;
    B += (size_t)z * sBb;

    // loader mapping: 2 threads per row, 16 floats each
    const int r    = tid >> 1;          // 0..127
    const int half = tid & 1;
    const float* Ap = A + (size_t)(m0 + r) * lda + half * 16;
    const float* Bp = (r < BN) ? (B + (size_t)(n0 + r) * ldb + half * 16) : nullptr;

    float acc[4][NI][4];
    #pragma unroll
    for (int mi = 0; mi < 4; mi++)
        #pragma unroll
        for (int ni = 0; ni < NI; ni++)
            #pragma unroll
            for (int c = 0; c < 4; c++) acc[mi][ni][c] = 0.f;

    const int nchunk = K >> 5;

    // ---- load chunk 0 into buf 0 ----
    {
        char* bh = sm + (r * LDSTRIDE + half * 16) * 2;
        #pragma unroll
        for (int j = 0; j < 4; j++) {
            float4 v = *(const float4*)(Ap + j * 4);
            split_store(bh + j * 8, bh + ASZB + j * 8, v);
        }
        if (Bp) {
            char* bb = sm + BHOFF + (r * LDSTRIDE + half * 16) * 2;
            #pragma unroll
            for (int j = 0; j < 4; j++) {
                float4 v = *(const float4*)(Bp + j * 4);
                split_store(bb + j * 8, bb + BSZB + j * 8, v);
            }
        }
    }
    __syncthreads();

    for (int c = 0; c < nchunk; c++) {
        const int buf = c & 1;
        const bool more = (c + 1 < nchunk);

        // prefetch next chunk into registers
        float4 pa[4], pb[4];
        if (more) {
            const int k0 = (c + 1) << 5;
            #pragma unroll
            for (int j = 0; j < 4; j++) pa[j] = *(const float4*)(Ap + k0 + j * 4);
            if (Bp) {
                #pragma unroll
                for (int j = 0; j < 4; j++) pb[j] = *(const float4*)(Bp + k0 + j * 4);
            }
        }

        // ---- compute 2 k16 steps from smem[buf] ----
        const uint32_t base = smu + buf * BUFSTR;
        #pragma unroll
        for (int kk = 0; kk < 32; kk += 16) {
            uint32_t bfh[NI][2], bfl[NI][2];
            #pragma unroll
            for (int p = 0; p < NP; p++) {
                const int ni = p * 2 + b_ni_off;
                const int n = wn * WN + ni * 8 + lr;
                const uint32_t ab = base + BHOFF + (uint32_t)(n * LDSTRIDE + kk + b_k_off) * 2;
                ldsm_x4(bfh[p*2][0], bfh[p*2][1], bfh[p*2+1][0], bfh[p*2+1][1], ab);
                ldsm_x4(bfl[p*2][0], bfl[p*2][1], bfl[p*2+1][0], bfl[p*2+1][1], ab + BSZB);
            }
            #pragma unroll
            for (int mi = 0; mi < 4; mi++) {
                const int row = wm * 64 + mi * 16 + a_row_off;
                const uint32_t aa = base + (uint32_t)(row * LDSTRIDE + kk + a_k_off) * 2;
                uint32_t ah0, ah1, ah2, ah3, al0, al1, al2, al3;
                ldsm_x4(ah0, ah1, ah2, ah3, aa);
                ldsm_x4(al0, al1, al2, al3, aa + ASZB);
                #pragma unroll
                for (int ni = 0; ni < NI; ni++) {
                    mma16816(acc[mi][ni], ah0, ah1, ah2, ah3, bfh[ni][0], bfh[ni][1]);
                    mma16816(acc[mi][ni], ah0, ah1, ah2, ah3, bfl[ni][0], bfl[ni][1]);
                    mma16816(acc[mi][ni], al0, al1, al2, al3, bfh[ni][0], bfh[ni][1]);
                }
            }
        }

        if (more) {
            __syncthreads();
            char* bh = sm + (buf ^ 1) * BUFSTR + (r * LDSTRIDE + half * 16) * 2;
            #pragma unroll
            for (int j = 0; j < 4; j++)
                split_store(bh + j * 8, bh + ASZB + j * 8, pa[j]);
            if (Bp) {
                char* bb = sm + (buf ^ 1) * BUFSTR + BHOFF + (r * LDSTRIDE + half * 16) * 2;
                #pragma unroll
                for (int j = 0; j < 4; j++)
                    split_store(bb + j * 8, bb + BSZB + j * 8, pb[j]);
            }
            __syncthreads();
        }
    }

    // ---- epilogue from register accumulators ----
    const bool hasb = (bias != nullptr);
    #pragma unroll
    for (int mi = 0; mi < 4; mi++) {
        #pragma unroll
        for (int ni = 0; ni < NI; ni++) {
            const int row0 = m0 + wm * 64 + mi * 16 + g;
            const int row1 = row0 + 8;
            const int col  = n0 + wn * WN + ni * 8 + 2 * t;
            float b0 = hasb ? bias[col]     : 0.f;
            float b1 = hasb ? bias[col + 1] : 0.f;
            float v0 = acc[mi][ni][0] * scale + b0;
            float v1 = acc[mi][ni][1] * scale + b1;
            float v2 = acc[mi][ni][2] * scale + b0;
            float v3 = acc[mi][ni][3] * scale + b1;
            if (mode == EP_F32) {
                float* o = out + (size_t)z * sOb;
                *(float2*)(o + (size_t)row0 * ldo + col) = make_float2(v0, v1);
                *(float2*)(o + (size_t)row1 * ldo + col) = make_float2(v2, v3);
            } else if (mode == EP_QK) {
                int h = col >> 6, dk = col & 63;
                int b_0 = row0 >> 11, s_0 = row0 & (SS - 1);
                int b_1 = row1 >> 11, s_1 = row1 & (SS - 1);
                *(float2*)(out + ((size_t)(b_0 * NH + h) * SS + s_0) * DK + dk) = make_float2(v0, v1);
                *(float2*)(out + ((size_t)(b_1 * NH + h) * SS + s_1) * DK + dk) = make_float2(v2, v3);
            } else if (mode == EP_VT) {
                int h = col >> 6, dk = col & 63;
                int b_0 = row0 >> 11, s_0 = row0 & (SS - 1);
                int b_1 = row1 >> 11, s_1 = row1 & (SS - 1);
                out[((size_t)(b_0 * NH + h) * DK + dk)     * SS + s_0] = v0;
                out[((size_t)(b_0 * NH + h) * DK + dk + 1) * SS + s_0] = v1;
                out[((size_t)(b_1 * NH + h) * DK + dk)     * SS + s_1] = v2;
                out[((size_t)(b_1 * NH + h) * DK + dk + 1) * SS + s_1] = v3;
            } else { // EP_CTX
                int bb = z >> 4, h = z & 15;
                *(float2*)(out + ((size_t)(bb * SS) + row0) * DM + h * DK + col) = make_float2(v0, v1);
                *(float2*)(out + ((size_t)(bb * SS) + row1) * DM + h * DK + col) = make_float2(v2, v3);
            }
        }
    }
}

// ---------------------------------------------------------------------------
// W [K,N] -> W^T [N,K]
// ---------------------------------------------------------------------------
__global__ void transpose_kernel(const float* __restrict__ src, float* __restrict__ dst)
{
    __shared__ float tile[32][33];
    int bx = blockIdx.x * 32, by = blockIdx.y * 32;
    int tx = threadIdx.x, ty = threadIdx.y;
    #pragma unroll
    for (int i = 0; i < 32; i += 8)
        tile[ty + i][tx] = src[(size_t)(by + ty + i) * DM + bx + tx];
    __syncthreads();
    #pragma unroll
    for (int i = 0; i < 32; i += 8)
        dst[(size_t)(bx + ty + i) * DM + by + tx] = tile[tx][ty + i];
}

// ---------------------------------------------------------------------------
// Softmax: one block per row of 2048.
// ---------------------------------------------------------------------------
__global__ void __launch_bounds__(256) softmax_kernel(float* __restrict__ attn)
{
    __shared__ float redm[8];
    __shared__ float reds[8];
    const int tid = threadIdx.x;
    float* p = attn + (size_t)blockIdx.x * SS;

    float4 v0 = *(float4*)&p[tid*8];
    float4 v1 = *(float4*)&p[tid*8 + 4];

    float m = fmaxf(fmaxf(fmaxf(v0.x, v0.y), fmaxf(v0.z, v0.w)),
                    fmaxf(fmaxf(v1.x, v1.y), fmaxf(v1.z, v1.w)));
    #pragma unroll
    for (int o = 16; o > 0; o >>= 1) m = fmaxf(m, __shfl_xor_sync(0xffffffffu, m, o));
    if ((tid & 31) == 0) redm[tid >> 5] = m;
    __syncthreads();
    float rowmax = redm[0];
    #pragma unroll
    for (int i = 1; i < 8; i++) rowmax = fmaxf(rowmax, redm[i]);

    v0.x = __expf(v0.x - rowmax); v0.y = __expf(v0.y - rowmax);
    v0.z = __expf(v0.z - rowmax); v0.w = __expf(v0.w - rowmax);
    v1.x = __expf(v1.x - rowmax); v1.y = __expf(v1.y - rowmax);
    v1.z = __expf(v1.z - rowmax); v1.w = __expf(v1.w - rowmax);

    float s = v0.x + v0.y + v0.z + v0.w + v1.x + v1.y + v1.z + v1.w;
    #pragma unroll
    for (int o = 16; o > 0; o >>= 1) s += __shfl_xor_sync(0xffffffffu, s, o);
    if ((tid & 31) == 0) reds[tid >> 5] = s;
    __syncthreads();
    float rowsum = 0.f;
    #pragma unroll
    for (int i = 0; i < 8; i++) rowsum += reds[i];
    float invs = 1.0f / rowsum;

    v0.x *= invs; v0.y *= invs; v0.z *= invs; v0.w *= invs;
    v1.x *= invs; v1.y *= invs; v1.z *= invs; v1.w *= invs;
    *(float4*)&p[tid*8]     = v0;
    *(float4*)&p[tid*8 + 4] = v1;
}

// ---------------------------------------------------------------------------
extern "C" void kernel_launch(void* const* d_in, const int* in_sizes, int n_in,
                              void* d_out, int out_size)
{
    const float* q  = (const float*)d_in[0];
    const float* k  = (const float*)d_in[1];
    const float* v  = (const float*)d_in[2];
    const float* Wq = (const float*)d_in[3];
    const float* bq = (const float*)d_in[4];
    const float* Wk = (const float*)d_in[5];
    const float* bk = (const float*)d_in[6];
    const float* Wv = (const float*)d_in[7];
    const float* bv = (const float*)d_in[8];
    const float* Wo = (const float*)d_in[9];
    const float* bo = (const float*)d_in[10];

    float* out  = (float*)d_out;
    float* attn = out + (size_t)MROWS * DM;

    void *wt, *qh, *kh, *vt, *ctx;
    cudaGetSymbolAddress(&wt,  g_wt);
    cudaGetSymbolAddress(&qh,  g_qh);
    cudaGetSymbolAddress(&kh,  g_kh);
    cudaGetSymbolAddress(&vt,  g_vt);
    cudaGetSymbolAddress(&ctx, g_ctx);
    float* wtq = (float*)wt;
    float* wtk = wtq + (size_t)DM*DM;
    float* wtv = wtk + (size_t)DM*DM;
    float* wto = wtv + (size_t)DM*DM;

    // dynamic smem sizes
    const int smem128 = 2 * (2*ASZB + 2*128*LDSTRIDE*2);  // 81920
    const int smem64  = 2 * (2*ASZB + 2*64*LDSTRIDE*2);   // 61440
    cudaFuncSetAttribute(gemm_hmma_kernel<128>,
                         cudaFuncAttributeMaxDynamicSharedMemorySize, smem128);
    cudaFuncSetAttribute(gemm_hmma_kernel<64>,
                         cudaFuncAttributeMaxDynamicSharedMemorySize, smem64);

    dim3 tgrid(32, 32), tblk(32, 8);
    transpose_kernel<<<tgrid, tblk>>>(Wq, wtq);
    transpose_kernel<<<tgrid, tblk>>>(Wk, wtk);
    transpose_kernel<<<tgrid, tblk>>>(Wv, wtv);
    transpose_kernel<<<tgrid, tblk>>>(Wo, wto);

    // QKV projections (M=4096, N=1024, K=1024)
    gemm_hmma_kernel<128><<<dim3(8, 32, 1), 256, smem128>>>(
        q, DM, 0, wtq, DM, 0, DM, bq, (float*)qh, 0, 0, 1.f, EP_QK);
    gemm_hmma_kernel<128><<<dim3(8, 32, 1), 256, smem128>>>(
        k, DM, 0, wtk, DM, 0, DM, bk, (float*)kh, 0, 0, 1.f, EP_QK);
    gemm_hmma_kernel<128><<<dim3(8, 32, 1), 256, smem128>>>(
        v, DM, 0, wtv, DM, 0, DM, bv, (float*)vt, 0, 0, 1.f, EP_VT);

    // scores = QK^T / 8 (per bh: M=N=2048, K=64)
    gemm_hmma_kernel<128><<<dim3(16, 16, 32), 256, smem128>>>(
        (const float*)qh, DK, (size_t)SS*DK,
        (const float*)kh, DK, (size_t)SS*DK,
        DK, nullptr, attn, SS, (size_t)SS*SS, 0.125f, EP_F32);

    // softmax in place
    softmax_kernel<<<NBH * SS, 256>>>(attn);

    // ctx = attn @ V (per bh: M=2048, N=64, K=2048)
    gemm_hmma_kernel<64><<<dim3(1, 16, 32), 256, smem64>>>(
        attn, SS, (size_t)SS*SS,
        (const float*)vt, SS, (size_t)DK*SS,
        SS, nullptr, (float*)ctx, 0, 0, 1.f, EP_CTX);

    // out = ctx @ Wo + bo
    gemm_hmma_kernel<128><<<dim3(8, 32, 1), 256, smem128>>>(
        (const float*)ctx, DM, 0, wto, DM, 0, DM, bo, out, DM, 0, 1.f, EP_F32);
}

// round 7
// speedup vs baseline: 1.7560x; 1.0190x over previous
#include <cuda_runtime.h>
#include <cuda_bf16.h>
#include <cstdint>

#define NB 2
#define NH 16
#define SS 2048
#define DK 64
#define DM 1024
#define NBH (NB*NH)     // 32
#define MROWS (NB*SS)   // 4096

// ---------------- scratch (allocation-free rule) ----------------
__device__ __align__(256) float g_wt[4][DM*DM];     // W^T (K-major) q,k,v,o
__device__ __align__(256) float g_qh[NBH*SS*DK];    // [bh][s][dk]
__device__ __align__(256) float g_kh[NBH*SS*DK];
__device__ __align__(256) float g_vt[NBH*DK*SS];    // [bh][dk][s]
__device__ __align__(256) float g_ctx[(size_t)MROWS*DM];
__device__ __align__(256) float2 g_stats[NBH*SS];   // per-row (max, sum)

// ---------------- epilogue modes ----------------
#define EP_F32 0
#define EP_QK  1
#define EP_VT  2

// fp32 -> bf16 hi + residual lo (packed pairs). low half = first elem.
__device__ __forceinline__ uint32_t split2(float a, float b, uint32_t& lo) {
    __nv_bfloat162 h = __floats2bfloat162_rn(a, b);
    __nv_bfloat162 l = __floats2bfloat162_rn(a - __low2float(h), b - __high2float(h));
    lo = reinterpret_cast<uint32_t&>(l);
    return reinterpret_cast<uint32_t&>(h);
}

__device__ __forceinline__ void mma16816(float* c,
                                         uint32_t a0, uint32_t a1, uint32_t a2, uint32_t a3,
                                         uint32_t b0, uint32_t b1) {
    asm volatile(
        "mma.sync.aligned.m16n8k16.row.col.f32.bf16.bf16.f32 "
        "{%0,%1,%2,%3}, {%4,%5,%6,%7}, {%8,%9}, {%0,%1,%2,%3};"
        : "+f"(c[0]), "+f"(c[1]), "+f"(c[2]), "+f"(c[3])
        : "r"(a0), "r"(a1), "r"(a2), "r"(a3), "r"(b0), "r"(b1));
}

__device__ __forceinline__ void ldsm_x4(uint32_t& r0, uint32_t& r1,
                                        uint32_t& r2, uint32_t& r3, uint32_t a) {
    asm volatile("ldmatrix.sync.aligned.m8n8.x4.shared.b16 {%0,%1,%2,%3}, [%4];"
        : "=r"(r0), "=r"(r1), "=r"(r2), "=r"(r3) : "r"(a));
}

#define LDSTRIDE 40
#define ASZB (128 * LDSTRIDE * 2)

__device__ __forceinline__ void split_store(char* dst_h, char* dst_l, float4 v) {
    uint32_t l0, l1;
    uint32_t h0 = split2(v.x, v.y, l0);
    uint32_t h1 = split2(v.z, v.w, l1);
    *(uint2*)dst_h = make_uint2(h0, h1);
    *(uint2*)dst_l = make_uint2(l0, l1);
}

// ---------------------------------------------------------------------------
// Generic HMMA bf16-split GEMM (projections). C tile 128 x 128, BK=32.
// ---------------------------------------------------------------------------
template<int BN>
__global__ void __launch_bounds__(256)
gemm_hmma_kernel(const float* __restrict__ A, int lda, size_t sAb,
                 const float* __restrict__ B, int ldb, size_t sBb,
                 int K,
                 const float* __restrict__ bias,
                 float* __restrict__ out, int ldo, size_t sOb,
                 float scale, int mode)
{
    constexpr int WN = BN / 4;
    constexpr int NI = WN / 8;
    constexpr int NP = NI / 2;
    constexpr int BSZB = BN * LDSTRIDE * 2;
    constexpr int BHOFF = 2 * ASZB;
    constexpr int BUFSTR = 2 * ASZB + 2 * BSZB;

    extern __shared__ char sm[];
    const uint32_t smu = (uint32_t)__cvta_generic_to_shared(sm);

    const int tid  = threadIdx.x;
    const int wid  = tid >> 5;
    const int lane = tid & 31;
    const int g = lane >> 2;
    const int t = lane & 3;
    const int wm = wid & 1;
    const int wn = wid >> 1;

    const int lmat = lane >> 3;
    const int lr   = lane & 7;
    const int a_row_off = (lmat & 1) * 8 + lr;
    const int a_k_off   = (lmat >> 1) * 8;
    const int b_ni_off  = (lmat >> 1);
    const int b_k_off   = (lmat & 1) * 8;

    const int m0 = blockIdx.y * 128;
    const int n0 = blockIdx.x * BN;
    const int z  = blockIdx.z;
    A += (size_t)z * sAb;
    B += (size_t)z * sBb;

    const int r    = tid >> 1;
    const int half = tid & 1;
    const float* Ap = A + (size_t)(m0 + r) * lda + half * 16;
    const float* Bp = (r < BN) ? (B + (size_t)(n0 + r) * ldb + half * 16) : nullptr;

    float acc[4][NI][4];
    #pragma unroll
    for (int mi = 0; mi < 4; mi++)
        #pragma unroll
        for (int ni = 0; ni < NI; ni++)
            #pragma unroll
            for (int c = 0; c < 4; c++) acc[mi][ni][c] = 0.f;

    const int nchunk = K >> 5;

    {
        char* bh = sm + (r * LDSTRIDE + half * 16) * 2;
        #pragma unroll
        for (int j = 0; j < 4; j++) {
            float4 v = *(const float4*)(Ap + j * 4);
            split_store(bh + j * 8, bh + ASZB + j * 8, v);
        }
        if (Bp) {
            char* bb = sm + BHOFF + (r * LDSTRIDE + half * 16) * 2;
            #pragma unroll
            for (int j = 0; j < 4; j++) {
                float4 v = *(const float4*)(Bp + j * 4);
                split_store(bb + j * 8, bb + BSZB + j * 8, v);
            }
        }
    }
    __syncthreads();

    for (int c = 0; c < nchunk; c++) {
        const int buf = c & 1;
        const bool more = (c + 1 < nchunk);

        float4 pa[4], pb[4];
        if (more) {
            const int k0 = (c + 1) << 5;
            #pragma unroll
            for (int j = 0; j < 4; j++) pa[j] = *(const float4*)(Ap + k0 + j * 4);
            if (Bp) {
                #pragma unroll
                for (int j = 0; j < 4; j++) pb[j] = *(const float4*)(Bp + k0 + j * 4);
            }
        }

        const uint32_t base = smu + buf * BUFSTR;
        #pragma unroll
        for (int kk = 0; kk < 32; kk += 16) {
            uint32_t bfh[NI][2], bfl[NI][2];
            #pragma unroll
            for (int p = 0; p < NP; p++) {
                const int ni = p * 2 + b_ni_off;
                const int n = wn * WN + ni * 8 + lr;
                const uint32_t ab = base + BHOFF + (uint32_t)(n * LDSTRIDE + kk + b_k_off) * 2;
                ldsm_x4(bfh[p*2][0], bfh[p*2][1], bfh[p*2+1][0], bfh[p*2+1][1], ab);
                ldsm_x4(bfl[p*2][0], bfl[p*2][1], bfl[p*2+1][0], bfl[p*2+1][1], ab + BSZB);
            }
            #pragma unroll
            for (int mi = 0; mi < 4; mi++) {
                const int row = wm * 64 + mi * 16 + a_row_off;
                const uint32_t aa = base + (uint32_t)(row * LDSTRIDE + kk + a_k_off) * 2;
                uint32_t ah0, ah1, ah2, ah3, al0, al1, al2, al3;
                ldsm_x4(ah0, ah1, ah2, ah3, aa);
                ldsm_x4(al0, al1, al2, al3, aa + ASZB);
                #pragma unroll
                for (int ni = 0; ni < NI; ni++) {
                    mma16816(acc[mi][ni], ah0, ah1, ah2, ah3, bfh[ni][0], bfh[ni][1]);
                    mma16816(acc[mi][ni], ah0, ah1, ah2, ah3, bfl[ni][0], bfl[ni][1]);
                    mma16816(acc[mi][ni], al0, al1, al2, al3, bfh[ni][0], bfh[ni][1]);
                }
            }
        }

        if (more) {
            __syncthreads();
            char* bh = sm + (buf ^ 1) * BUFSTR + (r * LDSTRIDE + half * 16) * 2;
            #pragma unroll
            for (int j = 0; j < 4; j++)
                split_store(bh + j * 8, bh + ASZB + j * 8, pa[j]);
            if (Bp) {
                char* bb = sm + (buf ^ 1) * BUFSTR + BHOFF + (r * LDSTRIDE + half * 16) * 2;
                #pragma unroll
                for (int j = 0; j < 4; j++)
                    split_store(bb + j * 8, bb + BSZB + j * 8, pb[j]);
            }
            __syncthreads();
        }
    }

    const bool hasb = (bias != nullptr);
    #pragma unroll
    for (int mi = 0; mi < 4; mi++) {
        #pragma unroll
        for (int ni = 0; ni < NI; ni++) {
            const int row0 = m0 + wm * 64 + mi * 16 + g;
            const int row1 = row0 + 8;
            const int col  = n0 + wn * WN + ni * 8 + 2 * t;
            float b0 = hasb ? bias[col]     : 0.f;
            float b1 = hasb ? bias[col + 1] : 0.f;
            float v0 = acc[mi][ni][0] * scale + b0;
            float v1 = acc[mi][ni][1] * scale + b1;
            float v2 = acc[mi][ni][2] * scale + b0;
            float v3 = acc[mi][ni][3] * scale + b1;
            if (mode == EP_F32) {
                float* o = out + (size_t)z * sOb;
                *(float2*)(o + (size_t)row0 * ldo + col) = make_float2(v0, v1);
                *(float2*)(o + (size_t)row1 * ldo + col) = make_float2(v2, v3);
            } else if (mode == EP_QK) {
                int h = col >> 6, dk = col & 63;
                int b_0 = row0 >> 11, s_0 = row0 & (SS - 1);
                int b_1 = row1 >> 11, s_1 = row1 & (SS - 1);
                *(float2*)(out + ((size_t)(b_0 * NH + h) * SS + s_0) * DK + dk) = make_float2(v0, v1);
                *(float2*)(out + ((size_t)(b_1 * NH + h) * SS + s_1) * DK + dk) = make_float2(v2, v3);
            } else { // EP_VT
                int h = col >> 6, dk = col & 63;
                int b_0 = row0 >> 11, s_0 = row0 & (SS - 1);
                int b_1 = row1 >> 11, s_1 = row1 & (SS - 1);
                out[((size_t)(b_0 * NH + h) * DK + dk)     * SS + s_0] = v0;
                out[((size_t)(b_0 * NH + h) * DK + dk + 1) * SS + s_0] = v1;
                out[((size_t)(b_1 * NH + h) * DK + dk)     * SS + s_1] = v2;
                out[((size_t)(b_1 * NH + h) * DK + dk + 1) * SS + s_1] = v3;
            }
        }
    }
}

// ===========================================================================
// Fused attention. M-split: warp w owns rows w*16..w*16+15, all 2048 cols.
// Smem tiles: Q/K rows 64 bf16 @ stride 72 elems (144 B), V rows 128 bf16
// @ stride 136 elems (272 B). All strides ≡ 16 (mod 128) -> ldmatrix clean.
// ===========================================================================
#define QSTR 144
#define VSTR 272
#define QHOF 0
#define QLOF 18432            // 128*144
#define KHOF 36864
#define KLOF 55296
#define S1_SMEM 73728
#define VHOF 73728
#define VLOF 91136            // +64*272
#define S2_SMEM 108544

#define SCALE_QK 0.125f

// ---- pass 1: online softmax stats ----
__global__ void __launch_bounds__(256) attn_stats_kernel()
{
    extern __shared__ char sm[];
    const uint32_t smu = (uint32_t)__cvta_generic_to_shared(sm);
    const int tid = threadIdx.x;
    const int w = tid >> 5;
    const int lane = tid & 31;
    const int g = lane >> 2, t = lane & 3;
    const int lmat = lane >> 3, lr = lane & 7;
    const int a_row_off = (lmat & 1) * 8 + lr;
    const int a_k_off   = (lmat >> 1) * 8;
    const int b_ni_off  = (lmat >> 1);
    const int b_k_off   = (lmat & 1) * 8;

    const int m0 = blockIdx.x * 128;
    const int bh = blockIdx.y;
    const float* Q  = g_qh + (size_t)bh * SS * DK;
    const float* Kg = g_kh + (size_t)bh * SS * DK;

    // load Q tile (persistent)
    {
        const int r = tid >> 1, half = tid & 1;
        const float* p = Q + (size_t)(m0 + r) * DK + half * 32;
        char* d = sm + QHOF + r * QSTR + half * 64;
        #pragma unroll
        for (int j = 0; j < 8; j++)
            split_store(d + j * 8, d + (QLOF - QHOF) + j * 8, *(const float4*)(p + j * 4));
    }

    // hoist Q fragments (after first sync)
    uint32_t aqh[4][4], aql[4][4];
    float m[2] = {-1e30f, -1e30f}, s[2] = {0.f, 0.f};

    for (int j = 0; j < 16; j++) {
        if (j > 0) __syncthreads();
        // load K chunk
        {
            const int r = tid >> 1, half = tid & 1;
            const float* p = Kg + (size_t)(j * 128 + r) * DK + half * 32;
            char* d = sm + KHOF + r * QSTR + half * 64;
            #pragma unroll
            for (int q = 0; q < 8; q++)
                split_store(d + q * 8, d + (KLOF - KHOF) + q * 8, *(const float4*)(p + q * 4));
        }
        __syncthreads();

        if (j == 0) {
            #pragma unroll
            for (int kk = 0; kk < 4; kk++) {
                const int row = w * 16 + a_row_off;
                const uint32_t aa = smu + QHOF + (uint32_t)(row * QSTR) + (kk * 16 + a_k_off) * 2;
                ldsm_x4(aqh[kk][0], aqh[kk][1], aqh[kk][2], aqh[kk][3], aa);
                ldsm_x4(aql[kk][0], aql[kk][1], aql[kk][2], aql[kk][3], aa + (QLOF - QHOF));
            }
        }

        float acc[16][4];
        #pragma unroll
        for (int ni = 0; ni < 16; ni++)
            #pragma unroll
            for (int c = 0; c < 4; c++) acc[ni][c] = 0.f;

        #pragma unroll
        for (int kk = 0; kk < 4; kk++) {
            #pragma unroll
            for (int p = 0; p < 8; p++) {
                const int ni = p * 2 + b_ni_off;
                const int n = ni * 8 + lr;
                const uint32_t ab = smu + KHOF + (uint32_t)(n * QSTR) + (kk * 16 + b_k_off) * 2;
                uint32_t bh0, bh1, bh2, bh3, bl0, bl1, bl2, bl3;
                ldsm_x4(bh0, bh1, bh2, bh3, ab);
                ldsm_x4(bl0, bl1, bl2, bl3, ab + (KLOF - KHOF));
                mma16816(acc[p*2],   aqh[kk][0], aqh[kk][1], aqh[kk][2], aqh[kk][3], bh0, bh1);
                mma16816(acc[p*2],   aqh[kk][0], aqh[kk][1], aqh[kk][2], aqh[kk][3], bl0, bl1);
                mma16816(acc[p*2],   aql[kk][0], aql[kk][1], aql[kk][2], aql[kk][3], bh0, bh1);
                mma16816(acc[p*2+1], aqh[kk][0], aqh[kk][1], aqh[kk][2], aqh[kk][3], bh2, bh3);
                mma16816(acc[p*2+1], aqh[kk][0], aqh[kk][1], aqh[kk][2], aqh[kk][3], bl2, bl3);
                mma16816(acc[p*2+1], aql[kk][0], aql[kk][1], aql[kk][2], aql[kk][3], bh2, bh3);
            }
        }

        // online stats per row-half
        #pragma unroll
        for (int h2 = 0; h2 < 2; h2++) {
            float cm = -1e30f;
            #pragma unroll
            for (int ni = 0; ni < 16; ni++)
                cm = fmaxf(cm, fmaxf(acc[ni][h2*2], acc[ni][h2*2+1]));
            cm *= SCALE_QK;
            cm = fmaxf(cm, __shfl_xor_sync(0xffffffffu, cm, 1));
            cm = fmaxf(cm, __shfl_xor_sync(0xffffffffu, cm, 2));
            float mn = fmaxf(m[h2], cm);
            float sum = 0.f;
            #pragma unroll
            for (int ni = 0; ni < 16; ni++) {
                sum += __expf(acc[ni][h2*2]   * SCALE_QK - mn);
                sum += __expf(acc[ni][h2*2+1] * SCALE_QK - mn);
            }
            sum += __shfl_xor_sync(0xffffffffu, sum, 1);
            sum += __shfl_xor_sync(0xffffffffu, sum, 2);
            s[h2] = s[h2] * __expf(m[h2] - mn) + sum;
            m[h2] = mn;
        }
    }

    if (t == 0) {
        g_stats[(size_t)bh * SS + m0 + w * 16 + g]     = make_float2(m[0], s[0]);
        g_stats[(size_t)bh * SS + m0 + w * 16 + 8 + g] = make_float2(m[1], s[1]);
    }
}

// ---- pass 2: normalized weights (written once) + PV via register repack ----
__global__ void __launch_bounds__(256) attn_wv_kernel(float* __restrict__ attn)
{
    extern __shared__ char sm[];
    const uint32_t smu = (uint32_t)__cvta_generic_to_shared(sm);
    const int tid = threadIdx.x;
    const int w = tid >> 5;
    const int lane = tid & 31;
    const int g = lane >> 2, t = lane & 3;
    const int lmat = lane >> 3, lr = lane & 7;
    const int a_row_off = (lmat & 1) * 8 + lr;
    const int a_k_off   = (lmat >> 1) * 8;
    const int b_ni_off  = (lmat >> 1);
    const int b_k_off   = (lmat & 1) * 8;

    const int m0 = blockIdx.x * 128;
    const int bh = blockIdx.y;
    const int bb = bh >> 4, hh = bh & 15;
    const float* Q  = g_qh + (size_t)bh * SS * DK;
    const float* Kg = g_kh + (size_t)bh * SS * DK;
    const float* Vt = g_vt + (size_t)bh * DK * SS;
    float* attn_b = attn + (size_t)bh * SS * SS;

    // load Q tile (persistent)
    {
        const int r = tid >> 1, half = tid & 1;
        const float* p = Q + (size_t)(m0 + r) * DK + half * 32;
        char* d = sm + QHOF + r * QSTR + half * 64;
        #pragma unroll
        for (int j = 0; j < 8; j++)
            split_store(d + j * 8, d + (QLOF - QHOF) + j * 8, *(const float4*)(p + j * 4));
    }

    // per-thread stats for its two rows
    const int row0 = m0 + w * 16 + g;
    float2 st0 = g_stats[(size_t)bh * SS + row0];
    float2 st1 = g_stats[(size_t)bh * SS + row0 + 8];
    const float mm0 = st0.x, is0 = 1.f / st0.y;
    const float mm1 = st1.x, is1 = 1.f / st1.y;

    float ctx[8][4];
    #pragma unroll
    for (int ni = 0; ni < 8; ni++)
        #pragma unroll
        for (int c = 0; c < 4; c++) ctx[ni][c] = 0.f;

    for (int j = 0; j < 16; j++) {
        if (j > 0) __syncthreads();
        // load K chunk
        {
            const int r = tid >> 1, half = tid & 1;
            const float* p = Kg + (size_t)(j * 128 + r) * DK + half * 32;
            char* d = sm + KHOF + r * QSTR + half * 64;
            #pragma unroll
            for (int q = 0; q < 8; q++)
                split_store(d + q * 8, d + (KLOF - KHOF) + q * 8, *(const float4*)(p + q * 4));
        }
        // load V chunk (64 dk rows x 128 s)
        {
            const int vr = tid >> 2, q4 = tid & 3;
            const float* p = Vt + (size_t)vr * SS + j * 128 + q4 * 32;
            char* d = sm + VHOF + vr * VSTR + q4 * 64;
            #pragma unroll
            for (int q = 0; q < 8; q++)
                split_store(d + q * 8, d + (VLOF - VHOF) + q * 8, *(const float4*)(p + q * 4));
        }
        __syncthreads();

        // Q fragments
        uint32_t aqh[4][4], aql[4][4];
        #pragma unroll
        for (int kk = 0; kk < 4; kk++) {
            const int row = w * 16 + a_row_off;
            const uint32_t aa = smu + QHOF + (uint32_t)(row * QSTR) + (kk * 16 + a_k_off) * 2;
            ldsm_x4(aqh[kk][0], aqh[kk][1], aqh[kk][2], aqh[kk][3], aa);
            ldsm_x4(aql[kk][0], aql[kk][1], aql[kk][2], aql[kk][3], aa + (QLOF - QHOF));
        }

        float acc[16][4];
        #pragma unroll
        for (int ni = 0; ni < 16; ni++)
            #pragma unroll
            for (int c = 0; c < 4; c++) acc[ni][c] = 0.f;

        #pragma unroll
        for (int kk = 0; kk < 4; kk++) {
            #pragma unroll
            for (int p = 0; p < 8; p++) {
                const int ni = p * 2 + b_ni_off;
                const int n = ni * 8 + lr;
                const uint32_t ab = smu + KHOF + (uint32_t)(n * QSTR) + (kk * 16 + b_k_off) * 2;
                uint32_t bh0, bh1, bh2, bh3, bl0, bl1, bl2, bl3;
                ldsm_x4(bh0, bh1, bh2, bh3, ab);
                ldsm_x4(bl0, bl1, bl2, bl3, ab + (KLOF - KHOF));
                mma16816(acc[p*2],   aqh[kk][0], aqh[kk][1], aqh[kk][2], aqh[kk][3], bh0, bh1);
                mma16816(acc[p*2],   aqh[kk][0], aqh[kk][1], aqh[kk][2], aqh[kk][3], bl0, bl1);
                mma16816(acc[p*2],   aql[kk][0], aql[kk][1], aql[kk][2], aql[kk][3], bh0, bh1);
                mma16816(acc[p*2+1], aqh[kk][0], aqh[kk][1], aqh[kk][2], aqh[kk][3], bh2, bh3);
                mma16816(acc[p*2+1], aqh[kk][0], aqh[kk][1], aqh[kk][2], aqh[kk][3], bl2, bl3);
                mma16816(acc[p*2+1], aql[kk][0], aql[kk][1], aql[kk][2], aql[kk][3], bh2, bh3);
            }
        }

        // weights: w = exp(x*scale - m) / s  (bit-identical x to pass 1)
        #pragma unroll
        for (int ni = 0; ni < 16; ni++) {
            acc[ni][0] = __expf(acc[ni][0] * SCALE_QK - mm0) * is0;
            acc[ni][1] = __expf(acc[ni][1] * SCALE_QK - mm0) * is0;
            acc[ni][2] = __expf(acc[ni][2] * SCALE_QK - mm1) * is1;
            acc[ni][3] = __expf(acc[ni][3] * SCALE_QK - mm1) * is1;
        }

        // write normalized weights (the required attn output)
        {
            float* p0 = attn_b + (size_t)row0 * SS + j * 128 + 2 * t;
            float* p1 = attn_b + (size_t)(row0 + 8) * SS + j * 128 + 2 * t;
            #pragma unroll
            for (int ni = 0; ni < 16; ni++) {
                *(float2*)(p0 + ni * 8) = make_float2(acc[ni][0], acc[ni][1]);
                *(float2*)(p1 + ni * 8) = make_float2(acc[ni][2], acc[ni][3]);
            }
        }

        // PV: repack P fragments as A operands, V from smem as B
        #pragma unroll
        for (int u = 0; u < 8; u++) {
            uint32_t al0, al1, al2, al3;
            uint32_t ah0 = split2(acc[2*u][0],   acc[2*u][1],   al0);
            uint32_t ah1 = split2(acc[2*u][2],   acc[2*u][3],   al1);
            uint32_t ah2 = split2(acc[2*u+1][0], acc[2*u+1][1], al2);
            uint32_t ah3 = split2(acc[2*u+1][2], acc[2*u+1][3], al3);
            #pragma unroll
            for (int p = 0; p < 4; p++) {
                const int nv = (p * 2 + b_ni_off) * 8 + lr;
                const uint32_t ab = smu + VHOF + (uint32_t)(nv * VSTR) + (u * 16 + b_k_off) * 2;
                uint32_t vh0, vh1, vh2, vh3, vl0, vl1, vl2, vl3;
                ldsm_x4(vh0, vh1, vh2, vh3, ab);
                ldsm_x4(vl0, vl1, vl2, vl3, ab + (VLOF - VHOF));
                mma16816(ctx[p*2],   ah0, ah1, ah2, ah3, vh0, vh1);
                mma16816(ctx[p*2],   ah0, ah1, ah2, ah3, vl0, vl1);
                mma16816(ctx[p*2],   al0, al1, al2, al3, vh0, vh1);
                mma16816(ctx[p*2+1], ah0, ah1, ah2, ah3, vh2, vh3);
                mma16816(ctx[p*2+1], ah0, ah1, ah2, ah3, vl2, vl3);
                mma16816(ctx[p*2+1], al0, al1, al2, al3, vh2, vh3);
            }
        }
    }

    // ctx epilogue -> g_ctx[b*SS + row][h*64 + dk]
    #pragma unroll
    for (int ni = 0; ni < 8; ni++) {
        const int dk = ni * 8 + 2 * t;
        float* p0 = g_ctx + ((size_t)(bb * SS) + row0) * DM + hh * DK + dk;
        float* p1 = g_ctx + ((size_t)(bb * SS) + row0 + 8) * DM + hh * DK + dk;
        *(float2*)p0 = make_float2(ctx[ni][0], ctx[ni][1]);
        *(float2*)p1 = make_float2(ctx[ni][2], ctx[ni][3]);
    }
}

// ---------------------------------------------------------------------------
__global__ void transpose_kernel(const float* __restrict__ src, float* __restrict__ dst)
{
    __shared__ float tile[32][33];
    int bx = blockIdx.x * 32, by = blockIdx.y * 32;
    int tx = threadIdx.x, ty = threadIdx.y;
    #pragma unroll
    for (int i = 0; i < 32; i += 8)
        tile[ty + i][tx] = src[(size_t)(by + ty + i) * DM + bx + tx];
    __syncthreads();
    #pragma unroll
    for (int i = 0; i < 32; i += 8)
        dst[(size_t)(bx + ty + i) * DM + by + tx] = tile[tx][ty + i];
}

// ---------------------------------------------------------------------------
extern "C" void kernel_launch(void* const* d_in, const int* in_sizes, int n_in,
                              void* d_out, int out_size)
{
    const float* q  = (const float*)d_in[0];
    const float* k  = (const float*)d_in[1];
    const float* v  = (const float*)d_in[2];
    const float* Wq = (const float*)d_in[3];
    const float* bq = (const float*)d_in[4];
    const float* Wk = (const float*)d_in[5];
    const float* bk = (const float*)d_in[6];
    const float* Wv = (const float*)d_in[7];
    const float* bv = (const float*)d_in[8];
    const float* Wo = (const float*)d_in[9];
    const float* bo = (const float*)d_in[10];

    float* out  = (float*)d_out;
    float* attn = out + (size_t)MROWS * DM;

    void *wt, *qh, *kh, *vt, *ctx;
    cudaGetSymbolAddress(&wt,  g_wt);
    cudaGetSymbolAddress(&qh,  g_qh);
    cudaGetSymbolAddress(&kh,  g_kh);
    cudaGetSymbolAddress(&vt,  g_vt);
    cudaGetSymbolAddress(&ctx, g_ctx);
    float* wtq = (float*)wt;
    float* wtk = wtq + (size_t)DM*DM;
    float* wtv = wtk + (size_t)DM*DM;
    float* wto = wtv + (size_t)DM*DM;

    const int smem128 = 2 * (2*ASZB + 2*128*LDSTRIDE*2);  // 81920
    cudaFuncSetAttribute(gemm_hmma_kernel<128>,
                         cudaFuncAttributeMaxDynamicSharedMemorySize, smem128);
    cudaFuncSetAttribute(attn_stats_kernel,
                         cudaFuncAttributeMaxDynamicSharedMemorySize, S1_SMEM);
    cudaFuncSetAttribute(attn_wv_kernel,
                         cudaFuncAttributeMaxDynamicSharedMemorySize, S2_SMEM);

    dim3 tgrid(32, 32), tblk(32, 8);
    transpose_kernel<<<tgrid, tblk>>>(Wq, wtq);
    transpose_kernel<<<tgrid, tblk>>>(Wk, wtk);
    transpose_kernel<<<tgrid, tblk>>>(Wv, wtv);
    transpose_kernel<<<tgrid, tblk>>>(Wo, wto);

    // QKV projections
    gemm_hmma_kernel<128><<<dim3(8, 32, 1), 256, smem128>>>(
        q, DM, 0, wtq, DM, 0, DM, bq, (float*)qh, 0, 0, 1.f, EP_QK);
    gemm_hmma_kernel<128><<<dim3(8, 32, 1), 256, smem128>>>(
        k, DM, 0, wtk, DM, 0, DM, bk, (float*)kh, 0, 0, 1.f, EP_QK);
    gemm_hmma_kernel<128><<<dim3(8, 32, 1), 256, smem128>>>(
        v, DM, 0, wtv, DM, 0, DM, bv, (float*)vt, 0, 0, 1.f, EP_VT);

    // fused attention: stats pass, then weights+PV pass
    attn_stats_kernel<<<dim3(16, 32), 256, S1_SMEM>>>();
    attn_wv_kernel<<<dim3(16, 32), 256, S2_SMEM>>>(attn);

    // out = ctx @ Wo + bo
    gemm_hmma_kernel<128><<<dim3(8, 32, 1), 256, smem128>>>(
        (const float*)ctx, DM, 0, wto, DM, 0, DM, bo, out, DM, 0, 1.f, EP_F32);
}